// round 1
// baseline (speedup 1.0000x reference)
#include <cuda_runtime.h>

#define BATCH 4
#define SEQ   2048
#define DMODEL 1024
#define NHEAD 16
#define DK    64
#define NTOK  (BATCH*SEQ)    // 8192
#define BHTOT (BATCH*NHEAD)  // 64

// Scratch (static device globals — allocation-free per harness rules)
__device__ float g_Q[(size_t)BHTOT*SEQ*DK];
__device__ float g_K[(size_t)BHTOT*SEQ*DK];
__device__ float g_V[(size_t)BHTOT*SEQ*DK];
__device__ float g_ctx[(size_t)NTOK*DMODEL];
__device__ float g_Y[(size_t)NTOK*DMODEL];

// ---------------------------------------------------------------------------
// GEMM: out[t,e] = sum_d X[t,d]*W[e,d] + bias[e] (+resid[t,e])
// Tile 128x128x16, 256 threads, 8x8 per-thread microtile.
// layout: 0 = flat [t, e]; 1 = write e->(h,dk), t->(b,s) as [b,h,s,dk]
// ---------------------------------------------------------------------------
__global__ __launch_bounds__(256) void gemm_xwT(
    const float* __restrict__ X, const float* __restrict__ W,
    const float* __restrict__ bias, const float* __restrict__ resid,
    float* __restrict__ out, int bhsd_layout)
{
    __shared__ float sA[16][128];
    __shared__ float sB[16][128];
    const int tid = threadIdx.x;
    const int tx = tid & 15, ty = tid >> 4;
    const int bm = blockIdx.y * 128;
    const int bn = blockIdx.x * 128;

    float acc[8][8];
    #pragma unroll
    for (int i = 0; i < 8; i++)
        #pragma unroll
        for (int j = 0; j < 8; j++) acc[i][j] = 0.f;

    for (int k0 = 0; k0 < DMODEL; k0 += 16) {
        #pragma unroll
        for (int p = 0; p < 2; p++) {
            int idx = tid + p * 256;        // 512 float4s per operand
            int row = idx >> 2;             // 0..127
            int col4 = (idx & 3) * 4;       // 0,4,8,12
            float4 a = *(const float4*)&X[(size_t)(bm + row) * DMODEL + k0 + col4];
            sA[col4+0][row] = a.x; sA[col4+1][row] = a.y;
            sA[col4+2][row] = a.z; sA[col4+3][row] = a.w;
            float4 b = *(const float4*)&W[(size_t)(bn + row) * DMODEL + k0 + col4];
            sB[col4+0][row] = b.x; sB[col4+1][row] = b.y;
            sB[col4+2][row] = b.z; sB[col4+3][row] = b.w;
        }
        __syncthreads();
        #pragma unroll
        for (int k = 0; k < 16; k++) {
            float a[8], b[8];
            *(float4*)&a[0] = *(const float4*)&sA[k][ty * 8];
            *(float4*)&a[4] = *(const float4*)&sA[k][ty * 8 + 4];
            *(float4*)&b[0] = *(const float4*)&sB[k][tx * 8];
            *(float4*)&b[4] = *(const float4*)&sB[k][tx * 8 + 4];
            #pragma unroll
            for (int i = 0; i < 8; i++)
                #pragma unroll
                for (int j = 0; j < 8; j++)
                    acc[i][j] += a[i] * b[j];
        }
        __syncthreads();
    }

    #pragma unroll
    for (int i = 0; i < 8; i++) {
        int t = bm + ty * 8 + i;
        #pragma unroll
        for (int j = 0; j < 8; j++) {
            int e = bn + tx * 8 + j;
            float v = acc[i][j] + bias[e];
            if (resid) v += resid[(size_t)t * DMODEL + e];
            if (bhsd_layout) {
                int h = e >> 6, dki = e & 63;
                int bb = t >> 11, ss = t & 2047;
                out[(((size_t)bb * NHEAD + h) * SEQ + ss) * DK + dki] = v;
            } else {
                out[(size_t)t * DMODEL + e] = v;
            }
        }
    }
}

// ---------------------------------------------------------------------------
// Flash attention, fp32. CTA = (q-tile of 64, bh). 256 threads, 4x4 microtile.
// smem: sQ[k][r] (transposed), sKV shared K(transposed)/V(natural), sP[r][c].
// ---------------------------------------------------------------------------
__global__ __launch_bounds__(256) void flash_attn()
{
    __shared__ float sQ[64 * 64];
    __shared__ float sKV[64 * 64];
    __shared__ float sP[64 * 64];
    const int tid = threadIdx.x;
    const int tx = tid & 15, ty = tid >> 4;
    const int bh = blockIdx.y;
    const int q0 = blockIdx.x * 64;

    const float* Qg = g_Q + (size_t)bh * SEQ * DK + (size_t)q0 * DK;
    const float* Kg = g_K + (size_t)bh * SEQ * DK;
    const float* Vg = g_V + (size_t)bh * SEQ * DK;

    // Load Q tile transposed: sQ[k][r]
    #pragma unroll
    for (int p = 0; p < 4; p++) {
        int idx = tid + p * 256;
        int row = idx >> 4;
        int col = (idx & 15) * 4;
        float4 v = *(const float4*)&Qg[(size_t)row * DK + col];
        sQ[(col+0)*64 + row] = v.x; sQ[(col+1)*64 + row] = v.y;
        sQ[(col+2)*64 + row] = v.z; sQ[(col+3)*64 + row] = v.w;
    }

    float m[4], l[4], o[4][4];
    #pragma unroll
    for (int i = 0; i < 4; i++) {
        m[i] = -1e30f; l[i] = 0.f;
        #pragma unroll
        for (int j = 0; j < 4; j++) o[i][j] = 0.f;
    }

    for (int kt = 0; kt < SEQ; kt += 64) {
        __syncthreads();   // prev O-update done (protects sKV, sP); Q visible on first iter
        // Load K tile transposed: sKV[k][c]
        #pragma unroll
        for (int p = 0; p < 4; p++) {
            int idx = tid + p * 256;
            int row = idx >> 4;
            int col = (idx & 15) * 4;
            float4 v = *(const float4*)&Kg[(size_t)(kt + row) * DK + col];
            sKV[(col+0)*64 + row] = v.x; sKV[(col+1)*64 + row] = v.y;
            sKV[(col+2)*64 + row] = v.z; sKV[(col+3)*64 + row] = v.w;
        }
        __syncthreads();

        // S = Q K^T
        float s[4][4];
        #pragma unroll
        for (int i = 0; i < 4; i++)
            #pragma unroll
            for (int j = 0; j < 4; j++) s[i][j] = 0.f;
        #pragma unroll 16
        for (int k = 0; k < 64; k++) {
            float a[4], b[4];
            *(float4*)&a[0] = *(const float4*)&sQ[k * 64 + ty * 4];
            *(float4*)&b[0] = *(const float4*)&sKV[k * 64 + tx * 4];
            #pragma unroll
            for (int i = 0; i < 4; i++)
                #pragma unroll
                for (int j = 0; j < 4; j++)
                    s[i][j] += a[i] * b[j];
        }

        // Online softmax (row groups of 16 lanes: same ty, tx = 0..15)
        #pragma unroll
        for (int i = 0; i < 4; i++) {
            #pragma unroll
            for (int j = 0; j < 4; j++) s[i][j] *= 0.125f;   // 1/sqrt(64)
            float rm = fmaxf(fmaxf(s[i][0], s[i][1]), fmaxf(s[i][2], s[i][3]));
            #pragma unroll
            for (int off = 8; off; off >>= 1)
                rm = fmaxf(rm, __shfl_xor_sync(0xffffffffu, rm, off));
            float mn = fmaxf(m[i], rm);
            float alpha = __expf(m[i] - mn);
            float rs = 0.f;
            #pragma unroll
            for (int j = 0; j < 4; j++) { s[i][j] = __expf(s[i][j] - mn); rs += s[i][j]; }
            #pragma unroll
            for (int off = 8; off; off >>= 1)
                rs += __shfl_xor_sync(0xffffffffu, rs, off);
            l[i] = l[i] * alpha + rs;
            m[i] = mn;
            #pragma unroll
            for (int j = 0; j < 4; j++) o[i][j] *= alpha;
            *(float4*)&sP[(ty * 4 + i) * 64 + tx * 4] =
                make_float4(s[i][0], s[i][1], s[i][2], s[i][3]);
        }
        __syncthreads();

        // Load V tile (natural layout) into sKV: sKV[key][d]
        #pragma unroll
        for (int p = 0; p < 4; p++) {
            int idx = tid + p * 256;
            int row = idx >> 4;
            int col = (idx & 15) * 4;
            *(float4*)&sKV[row * 64 + col] =
                *(const float4*)&Vg[(size_t)(kt + row) * DK + col];
        }
        __syncthreads();

        // O += P @ V
        #pragma unroll 8
        for (int k = 0; k < 64; k++) {
            float4 v = *(const float4*)&sKV[k * 64 + tx * 4];
            #pragma unroll
            for (int i = 0; i < 4; i++) {
                float pv = sP[(ty * 4 + i) * 64 + k];
                o[i][0] += pv * v.x; o[i][1] += pv * v.y;
                o[i][2] += pv * v.z; o[i][3] += pv * v.w;
            }
        }
    }

    // Write ctx in [t, d] layout (d = h*64 + dk)
    const int b = bh >> 4, h = bh & 15;
    #pragma unroll
    for (int i = 0; i < 4; i++) {
        float inv = 1.f / l[i];
        int srow = q0 + ty * 4 + i;
        size_t base = ((size_t)(b * SEQ + srow)) * DMODEL + h * DK + tx * 4;
        *(float4*)&g_ctx[base] =
            make_float4(o[i][0]*inv, o[i][1]*inv, o[i][2]*inv, o[i][3]*inv);
    }
}

// ---------------------------------------------------------------------------
// LayerNorm over last dim (1024). One block (256 thr) per row.
// ---------------------------------------------------------------------------
__global__ __launch_bounds__(256) void ln_fused(
    const float* __restrict__ Y, const float* __restrict__ gamma,
    const float* __restrict__ beta, float* __restrict__ out)
{
    __shared__ float s_sum[8], s_sq[8];
    const int t = blockIdx.x;
    const int tid = threadIdx.x;
    const float* row = Y + (size_t)t * DMODEL;
    float4 v = *(const float4*)&row[tid * 4];
    float sum = v.x + v.y + v.z + v.w;
    float sq  = v.x*v.x + v.y*v.y + v.z*v.z + v.w*v.w;
    #pragma unroll
    for (int off = 16; off; off >>= 1) {
        sum += __shfl_xor_sync(0xffffffffu, sum, off);
        sq  += __shfl_xor_sync(0xffffffffu, sq,  off);
    }
    int w = tid >> 5;
    if ((tid & 31) == 0) { s_sum[w] = sum; s_sq[w] = sq; }
    __syncthreads();
    if (tid < 32) {
        sum = (tid < 8) ? s_sum[tid] : 0.f;
        sq  = (tid < 8) ? s_sq[tid]  : 0.f;
        #pragma unroll
        for (int off = 4; off; off >>= 1) {
            sum += __shfl_xor_sync(0xffffffffu, sum, off);
            sq  += __shfl_xor_sync(0xffffffffu, sq,  off);
        }
        if (tid == 0) { s_sum[0] = sum; s_sq[0] = sq; }
    }
    __syncthreads();
    float mu  = s_sum[0] * (1.f / DMODEL);
    float var = s_sq[0]  * (1.f / DMODEL) - mu * mu;
    float rstd = rsqrtf(var + 1e-5f);
    float4 g  = *(const float4*)&gamma[tid * 4];
    float4 bt = *(const float4*)&beta[tid * 4];
    float4 o4;
    o4.x = (v.x - mu) * rstd * g.x + bt.x;
    o4.y = (v.y - mu) * rstd * g.y + bt.y;
    o4.z = (v.z - mu) * rstd * g.z + bt.z;
    o4.w = (v.w - mu) * rstd * g.w + bt.w;
    *(float4*)&out[(size_t)t * DMODEL + tid * 4] = o4;
}

// ---------------------------------------------------------------------------
extern "C" void kernel_launch(void* const* d_in, const int* in_sizes, int n_in,
                              void* d_out, int out_size)
{
    const float* x     = (const float*)d_in[0];
    const float* Wq    = (const float*)d_in[1];
    const float* bq    = (const float*)d_in[2];
    const float* Wk    = (const float*)d_in[3];
    const float* bk    = (const float*)d_in[4];
    const float* Wv    = (const float*)d_in[5];
    const float* bv    = (const float*)d_in[6];
    const float* Wo    = (const float*)d_in[7];
    const float* bo    = (const float*)d_in[8];
    const float* gamma = (const float*)d_in[9];
    const float* beta  = (const float*)d_in[10];
    float* out = (float*)d_out;
    (void)in_sizes; (void)n_in; (void)out_size;

    float *gq, *gk, *gv, *gctx, *gy;
    cudaGetSymbolAddress((void**)&gq,   g_Q);
    cudaGetSymbolAddress((void**)&gk,   g_K);
    cudaGetSymbolAddress((void**)&gv,   g_V);
    cudaGetSymbolAddress((void**)&gctx, g_ctx);
    cudaGetSymbolAddress((void**)&gy,   g_Y);

    dim3 gg(DMODEL / 128, NTOK / 128);
    gemm_xwT<<<gg, 256>>>(x, Wq, bq, nullptr, gq, 1);
    gemm_xwT<<<gg, 256>>>(x, Wk, bk, nullptr, gk, 1);
    gemm_xwT<<<gg, 256>>>(x, Wv, bv, nullptr, gv, 1);
    flash_attn<<<dim3(SEQ / 64, BHTOT), 256>>>();
    gemm_xwT<<<gg, 256>>>(gctx, Wo, bo, x, gy, 0);
    ln_fused<<<NTOK, 256>>>(gy, gamma, beta, out);
}

// round 3
// speedup vs baseline: 1.5161x; 1.5161x over previous
#include <cuda_runtime.h>
#include <cuda_bf16.h>
#include <cstdint>

#define BATCH 4
#define SEQ   2048
#define DMODEL 1024
#define NHEAD 16
#define DK    64
#define NTOK  (BATCH*SEQ)    // 8192
#define BHTOT (BATCH*NHEAD)  // 64
#define WELEM (DMODEL*DMODEL)

// Scratch (static device globals — allocation-free per harness rules)
__device__ float g_Q[(size_t)BHTOT*SEQ*DK];
__device__ float g_K[(size_t)BHTOT*SEQ*DK];
__device__ float g_V[(size_t)BHTOT*SEQ*DK];
__device__ float g_ctx[(size_t)NTOK*DMODEL];
__device__ float g_Y[(size_t)NTOK*DMODEL];
// bf16 hi/lo scratch: activations (x, later reused for ctx) and 4 weights
__device__ __nv_bfloat16 g_ah[(size_t)NTOK*DMODEL];
__device__ __nv_bfloat16 g_al[(size_t)NTOK*DMODEL];
__device__ __nv_bfloat16 g_wh[(size_t)4*WELEM];
__device__ __nv_bfloat16 g_wl[(size_t)4*WELEM];

// ---------------------------------------------------------------------------
// fp32 -> bf16 hi/lo split (grid-stride, 4 elems/thread)
// ---------------------------------------------------------------------------
__global__ __launch_bounds__(256) void conv_hilo(
    const float* __restrict__ src, __nv_bfloat16* __restrict__ hi,
    __nv_bfloat16* __restrict__ lo, int n4)
{
    int i = blockIdx.x * blockDim.x + threadIdx.x;
    if (i >= n4) return;
    float4 v = *(const float4*)&src[(size_t)i * 4];
    __nv_bfloat16 h0 = __float2bfloat16_rn(v.x), h1 = __float2bfloat16_rn(v.y);
    __nv_bfloat16 h2 = __float2bfloat16_rn(v.z), h3 = __float2bfloat16_rn(v.w);
    __nv_bfloat162 H0(h0, h1), H1(h2, h3);
    __nv_bfloat162 L0(__float2bfloat16_rn(v.x - __bfloat162float(h0)),
                      __float2bfloat16_rn(v.y - __bfloat162float(h1)));
    __nv_bfloat162 L1(__float2bfloat16_rn(v.z - __bfloat162float(h2)),
                      __float2bfloat16_rn(v.w - __bfloat162float(h3)));
    *(uint2*)&hi[(size_t)i * 4] = make_uint2(*(uint32_t*)&H0, *(uint32_t*)&H1);
    *(uint2*)&lo[(size_t)i * 4] = make_uint2(*(uint32_t*)&L0, *(uint32_t*)&L1);
}

// ---------------------------------------------------------------------------
// mma.sync helpers
// ---------------------------------------------------------------------------
__device__ __forceinline__ void ldsm_x4(uint32_t (&r)[4], uint32_t addr) {
    asm volatile("ldmatrix.sync.aligned.m8n8.x4.shared.b16 {%0,%1,%2,%3}, [%4];"
        : "=r"(r[0]), "=r"(r[1]), "=r"(r[2]), "=r"(r[3]) : "r"(addr));
}
__device__ __forceinline__ void mma16816(float* d, const uint32_t* a, const uint32_t* b) {
    asm volatile(
        "mma.sync.aligned.m16n8k16.row.col.f32.bf16.bf16.f32 "
        "{%0,%1,%2,%3}, {%4,%5,%6,%7}, {%8,%9}, {%0,%1,%2,%3};"
        : "+f"(d[0]), "+f"(d[1]), "+f"(d[2]), "+f"(d[3])
        : "r"(a[0]), "r"(a[1]), "r"(a[2]), "r"(a[3]), "r"(b[0]), "r"(b[1]));
}

// ---------------------------------------------------------------------------
// Tensor-core GEMM (bf16x3): out[t,e] = sum_d X[t,d]*W[e,d] + bias[e] (+resid)
// CTA 128x128, 8 warps (2m x 4n), warp tile 64x32, K-chunk 32.
// smem rows: 32 bf16 + 8 pad = 80B stride (ldmatrix conflict-free).
// ---------------------------------------------------------------------------
#define LDAB 40   // bf16 elems per smem row (80 bytes)

__global__ __launch_bounds__(256, 2) void gemm_mma(
    const __nv_bfloat16* __restrict__ Ah, const __nv_bfloat16* __restrict__ Al,
    const __nv_bfloat16* __restrict__ Bh, const __nv_bfloat16* __restrict__ Bl,
    const float* __restrict__ bias, const float* __restrict__ resid,
    float* __restrict__ out, int bhsd_layout)
{
    __shared__ __nv_bfloat16 sAh[128 * LDAB], sAl[128 * LDAB];
    __shared__ __nv_bfloat16 sBh[128 * LDAB], sBl[128 * LDAB];

    const int tid = threadIdx.x;
    const int wid = tid >> 5, lane = tid & 31;
    const int bm = blockIdx.y * 128, bn = blockIdx.x * 128;
    const int wm = (wid >> 2) * 64;      // warp m offset
    const int wn = (wid & 3) * 32;       // warp n offset

    uint32_t sah, sal, sbh, sbl;
    asm("{ .reg .u64 t; cvta.to.shared.u64 t, %1; cvt.u32.u64 %0, t; }" : "=r"(sah) : "l"(sAh));
    asm("{ .reg .u64 t; cvta.to.shared.u64 t, %1; cvt.u32.u64 %0, t; }" : "=r"(sal) : "l"(sAl));
    asm("{ .reg .u64 t; cvta.to.shared.u64 t, %1; cvt.u32.u64 %0, t; }" : "=r"(sbh) : "l"(sBh));
    asm("{ .reg .u64 t; cvta.to.shared.u64 t, %1; cvt.u32.u64 %0, t; }" : "=r"(sbl) : "l"(sBl));

    float acc[4][4][4];
    #pragma unroll
    for (int i = 0; i < 4; i++)
        #pragma unroll
        for (int j = 0; j < 4; j++)
            #pragma unroll
            for (int k = 0; k < 4; k++) acc[i][j][k] = 0.f;

    // ldmatrix lane address components (byte offsets within a row / row select)
    const int a_row = lane & 15;                 // m row within 16
    const int a_kb  = ((lane >> 4) & 1) * 16;    // 0 or 16 bytes
    const int b_row = ((lane >> 4) & 1) * 8 + (lane & 7);  // n row within 16
    const int b_kb  = ((lane >> 3) & 1) * 16;

    for (int c = 0; c < DMODEL / 32; c++) {
        const int k0 = c * 32;
        __syncthreads();
        #pragma unroll
        for (int p = 0; p < 2; p++) {
            int idx = tid + p * 256;
            int r = idx >> 2;              // 0..127
            int ch = idx & 3;              // 16B chunk in row
            size_t ga = (size_t)(bm + r) * DMODEL + k0 + ch * 8;
            size_t gb = (size_t)(bn + r) * DMODEL + k0 + ch * 8;
            uint32_t so = (uint32_t)(r * 80 + ch * 16);
            *(uint4*)((char*)sAh + so) = *(const uint4*)&Ah[ga];
            *(uint4*)((char*)sAl + so) = *(const uint4*)&Al[ga];
            *(uint4*)((char*)sBh + so) = *(const uint4*)&Bh[gb];
            *(uint4*)((char*)sBl + so) = *(const uint4*)&Bl[gb];
        }
        __syncthreads();

        #pragma unroll
        for (int ks = 0; ks < 2; ks++) {
            const int kbase = ks * 32;
            // B fragments: hi and lo, 4 n-frags (two x4 loads each)
            uint32_t bh[4][2], bl[4][2];
            #pragma unroll
            for (int fp = 0; fp < 2; fp++) {
                uint32_t r4[4];
                uint32_t ba = (uint32_t)((wn + fp * 16 + b_row) * 80 + kbase + b_kb);
                ldsm_x4(r4, sbh + ba);
                bh[fp*2+0][0] = r4[0]; bh[fp*2+0][1] = r4[1];
                bh[fp*2+1][0] = r4[2]; bh[fp*2+1][1] = r4[3];
                ldsm_x4(r4, sbl + ba);
                bl[fp*2+0][0] = r4[0]; bl[fp*2+0][1] = r4[1];
                bl[fp*2+1][0] = r4[2]; bl[fp*2+1][1] = r4[3];
            }
            #pragma unroll
            for (int fm = 0; fm < 4; fm++) {
                uint32_t aa = (uint32_t)((wm + fm * 16 + a_row) * 80 + kbase + a_kb);
                uint32_t ah[4], al[4];
                ldsm_x4(ah, sah + aa);
                ldsm_x4(al, sal + aa);
                #pragma unroll
                for (int fn = 0; fn < 4; fn++) {
                    mma16816(acc[fm][fn], ah, bh[fn]);   // Ah*Bh
                    mma16816(acc[fm][fn], al, bh[fn]);   // Al*Bh
                    mma16816(acc[fm][fn], ah, bl[fn]);   // Ah*Bl
                }
            }
        }
    }

    // Epilogue: fragments -> gmem (float2 stores), bias + resid + layout
    const int qrow = lane >> 2;
    const int qcol = (lane & 3) * 2;
    #pragma unroll
    for (int fm = 0; fm < 4; fm++) {
        #pragma unroll
        for (int fn = 0; fn < 4; fn++) {
            int col = bn + wn + fn * 8 + qcol;
            float2 b2 = *(const float2*)&bias[col];
            #pragma unroll
            for (int h = 0; h < 2; h++) {
                int row = bm + wm + fm * 16 + qrow + h * 8;
                float2 v;
                v.x = acc[fm][fn][h * 2 + 0] + b2.x;
                v.y = acc[fm][fn][h * 2 + 1] + b2.y;
                if (resid) {
                    float2 r2 = *(const float2*)&resid[(size_t)row * DMODEL + col];
                    v.x += r2.x; v.y += r2.y;
                }
                if (bhsd_layout) {
                    int hh = col >> 6, dki = col & 63;
                    int bb = row >> 11, ss = row & 2047;
                    *(float2*)&out[(((size_t)bb * NHEAD + hh) * SEQ + ss) * DK + dki] = v;
                } else {
                    *(float2*)&out[(size_t)row * DMODEL + col] = v;
                }
            }
        }
    }
}

// ---------------------------------------------------------------------------
// Flash attention, fp32 (unchanged — verified correct)
// ---------------------------------------------------------------------------
__global__ __launch_bounds__(256) void flash_attn()
{
    __shared__ float sQ[64 * 64];
    __shared__ float sKV[64 * 64];
    __shared__ float sP[64 * 64];
    const int tid = threadIdx.x;
    const int tx = tid & 15, ty = tid >> 4;
    const int bh = blockIdx.y;
    const int q0 = blockIdx.x * 64;

    const float* Qg = g_Q + (size_t)bh * SEQ * DK + (size_t)q0 * DK;
    const float* Kg = g_K + (size_t)bh * SEQ * DK;
    const float* Vg = g_V + (size_t)bh * SEQ * DK;

    #pragma unroll
    for (int p = 0; p < 4; p++) {
        int idx = tid + p * 256;
        int row = idx >> 4;
        int col = (idx & 15) * 4;
        float4 v = *(const float4*)&Qg[(size_t)row * DK + col];
        sQ[(col+0)*64 + row] = v.x; sQ[(col+1)*64 + row] = v.y;
        sQ[(col+2)*64 + row] = v.z; sQ[(col+3)*64 + row] = v.w;
    }

    float m[4], l[4], o[4][4];
    #pragma unroll
    for (int i = 0; i < 4; i++) {
        m[i] = -1e30f; l[i] = 0.f;
        #pragma unroll
        for (int j = 0; j < 4; j++) o[i][j] = 0.f;
    }

    for (int kt = 0; kt < SEQ; kt += 64) {
        __syncthreads();
        #pragma unroll
        for (int p = 0; p < 4; p++) {
            int idx = tid + p * 256;
            int row = idx >> 4;
            int col = (idx & 15) * 4;
            float4 v = *(const float4*)&Kg[(size_t)(kt + row) * DK + col];
            sKV[(col+0)*64 + row] = v.x; sKV[(col+1)*64 + row] = v.y;
            sKV[(col+2)*64 + row] = v.z; sKV[(col+3)*64 + row] = v.w;
        }
        __syncthreads();

        float s[4][4];
        #pragma unroll
        for (int i = 0; i < 4; i++)
            #pragma unroll
            for (int j = 0; j < 4; j++) s[i][j] = 0.f;
        #pragma unroll 16
        for (int k = 0; k < 64; k++) {
            float a[4], b[4];
            *(float4*)&a[0] = *(const float4*)&sQ[k * 64 + ty * 4];
            *(float4*)&b[0] = *(const float4*)&sKV[k * 64 + tx * 4];
            #pragma unroll
            for (int i = 0; i < 4; i++)
                #pragma unroll
                for (int j = 0; j < 4; j++)
                    s[i][j] += a[i] * b[j];
        }

        #pragma unroll
        for (int i = 0; i < 4; i++) {
            #pragma unroll
            for (int j = 0; j < 4; j++) s[i][j] *= 0.125f;
            float rm = fmaxf(fmaxf(s[i][0], s[i][1]), fmaxf(s[i][2], s[i][3]));
            #pragma unroll
            for (int off = 8; off; off >>= 1)
                rm = fmaxf(rm, __shfl_xor_sync(0xffffffffu, rm, off));
            float mn = fmaxf(m[i], rm);
            float alpha = __expf(m[i] - mn);
            float rs = 0.f;
            #pragma unroll
            for (int j = 0; j < 4; j++) { s[i][j] = __expf(s[i][j] - mn); rs += s[i][j]; }
            #pragma unroll
            for (int off = 8; off; off >>= 1)
                rs += __shfl_xor_sync(0xffffffffu, rs, off);
            l[i] = l[i] * alpha + rs;
            m[i] = mn;
            #pragma unroll
            for (int j = 0; j < 4; j++) o[i][j] *= alpha;
            *(float4*)&sP[(ty * 4 + i) * 64 + tx * 4] =
                make_float4(s[i][0], s[i][1], s[i][2], s[i][3]);
        }
        __syncthreads();

        #pragma unroll
        for (int p = 0; p < 4; p++) {
            int idx = tid + p * 256;
            int row = idx >> 4;
            int col = (idx & 15) * 4;
            *(float4*)&sKV[row * 64 + col] =
                *(const float4*)&Vg[(size_t)(kt + row) * DK + col];
        }
        __syncthreads();

        #pragma unroll 8
        for (int k = 0; k < 64; k++) {
            float4 v = *(const float4*)&sKV[k * 64 + tx * 4];
            #pragma unroll
            for (int i = 0; i < 4; i++) {
                float pv = sP[(ty * 4 + i) * 64 + k];
                o[i][0] += pv * v.x; o[i][1] += pv * v.y;
                o[i][2] += pv * v.z; o[i][3] += pv * v.w;
            }
        }
    }

    const int b = bh >> 4, h = bh & 15;
    #pragma unroll
    for (int i = 0; i < 4; i++) {
        float inv = 1.f / l[i];
        int srow = q0 + ty * 4 + i;
        size_t base = ((size_t)(b * SEQ + srow)) * DMODEL + h * DK + tx * 4;
        *(float4*)&g_ctx[base] =
            make_float4(o[i][0]*inv, o[i][1]*inv, o[i][2]*inv, o[i][3]*inv);
    }
}

// ---------------------------------------------------------------------------
// LayerNorm (unchanged)
// ---------------------------------------------------------------------------
__global__ __launch_bounds__(256) void ln_fused(
    const float* __restrict__ Y, const float* __restrict__ gamma,
    const float* __restrict__ beta, float* __restrict__ out)
{
    __shared__ float s_sum[8], s_sq[8];
    const int t = blockIdx.x;
    const int tid = threadIdx.x;
    const float* row = Y + (size_t)t * DMODEL;
    float4 v = *(const float4*)&row[tid * 4];
    float sum = v.x + v.y + v.z + v.w;
    float sq  = v.x*v.x + v.y*v.y + v.z*v.z + v.w*v.w;
    #pragma unroll
    for (int off = 16; off; off >>= 1) {
        sum += __shfl_xor_sync(0xffffffffu, sum, off);
        sq  += __shfl_xor_sync(0xffffffffu, sq,  off);
    }
    int w = tid >> 5;
    if ((tid & 31) == 0) { s_sum[w] = sum; s_sq[w] = sq; }
    __syncthreads();
    if (tid < 32) {
        sum = (tid < 8) ? s_sum[tid] : 0.f;
        sq  = (tid < 8) ? s_sq[tid]  : 0.f;
        #pragma unroll
        for (int off = 4; off; off >>= 1) {
            sum += __shfl_xor_sync(0xffffffffu, sum, off);
            sq  += __shfl_xor_sync(0xffffffffu, sq,  off);
        }
        if (tid == 0) { s_sum[0] = sum; s_sq[0] = sq; }
    }
    __syncthreads();
    float mu  = s_sum[0] * (1.f / DMODEL);
    float var = s_sq[0]  * (1.f / DMODEL) - mu * mu;
    float rstd = rsqrtf(var + 1e-5f);
    float4 g  = *(const float4*)&gamma[tid * 4];
    float4 bt = *(const float4*)&beta[tid * 4];
    float4 o4;
    o4.x = (v.x - mu) * rstd * g.x + bt.x;
    o4.y = (v.y - mu) * rstd * g.y + bt.y;
    o4.z = (v.z - mu) * rstd * g.z + bt.z;
    o4.w = (v.w - mu) * rstd * g.w + bt.w;
    *(float4*)&out[(size_t)t * DMODEL + tid * 4] = o4;
}

// ---------------------------------------------------------------------------
extern "C" void kernel_launch(void* const* d_in, const int* in_sizes, int n_in,
                              void* d_out, int out_size)
{
    const float* x     = (const float*)d_in[0];
    const float* Wq    = (const float*)d_in[1];
    const float* bq    = (const float*)d_in[2];
    const float* Wk    = (const float*)d_in[3];
    const float* bk    = (const float*)d_in[4];
    const float* Wv    = (const float*)d_in[5];
    const float* bv    = (const float*)d_in[6];
    const float* Wo    = (const float*)d_in[7];
    const float* bo    = (const float*)d_in[8];
    const float* gamma = (const float*)d_in[9];
    const float* beta  = (const float*)d_in[10];
    float* out = (float*)d_out;
    (void)in_sizes; (void)n_in; (void)out_size;

    float *gq, *gk, *gv, *gctx, *gy;
    __nv_bfloat16 *ah, *al, *wh, *wl;
    cudaGetSymbolAddress((void**)&gq,   g_Q);
    cudaGetSymbolAddress((void**)&gk,   g_K);
    cudaGetSymbolAddress((void**)&gv,   g_V);
    cudaGetSymbolAddress((void**)&gctx, g_ctx);
    cudaGetSymbolAddress((void**)&gy,   g_Y);
    cudaGetSymbolAddress((void**)&ah,   g_ah);
    cudaGetSymbolAddress((void**)&al,   g_al);
    cudaGetSymbolAddress((void**)&wh,   g_wh);
    cudaGetSymbolAddress((void**)&wl,   g_wl);

    const int nx4 = NTOK * DMODEL / 4;     // x / ctx quads
    const int nw4 = WELEM / 4;             // weight quads

    // convert activations + weights to bf16 hi/lo
    conv_hilo<<<(nx4 + 255) / 256, 256>>>(x, ah, al, nx4);
    conv_hilo<<<(nw4 + 255) / 256, 256>>>(Wq, wh + 0*(size_t)WELEM, wl + 0*(size_t)WELEM, nw4);
    conv_hilo<<<(nw4 + 255) / 256, 256>>>(Wk, wh + 1*(size_t)WELEM, wl + 1*(size_t)WELEM, nw4);
    conv_hilo<<<(nw4 + 255) / 256, 256>>>(Wv, wh + 2*(size_t)WELEM, wl + 2*(size_t)WELEM, nw4);
    conv_hilo<<<(nw4 + 255) / 256, 256>>>(Wo, wh + 3*(size_t)WELEM, wl + 3*(size_t)WELEM, nw4);

    dim3 gg(DMODEL / 128, NTOK / 128);
    gemm_mma<<<gg, 256>>>(ah, al, wh + 0*(size_t)WELEM, wl + 0*(size_t)WELEM, bq, nullptr, gq, 1);
    gemm_mma<<<gg, 256>>>(ah, al, wh + 1*(size_t)WELEM, wl + 1*(size_t)WELEM, bk, nullptr, gk, 1);
    gemm_mma<<<gg, 256>>>(ah, al, wh + 2*(size_t)WELEM, wl + 2*(size_t)WELEM, bv, nullptr, gv, 1);

    flash_attn<<<dim3(SEQ / 64, BHTOT), 256>>>();

    // reuse activation hi/lo buffers for ctx (x itself still read as fp32 resid)
    conv_hilo<<<(nx4 + 255) / 256, 256>>>(gctx, ah, al, nx4);
    gemm_mma<<<gg, 256>>>(ah, al, wh + 3*(size_t)WELEM, wl + 3*(size_t)WELEM, bo, x, gy, 0);

    ln_fused<<<NTOK, 256>>>(gy, gamma, beta, out);
}

// round 5
// speedup vs baseline: 3.0023x; 1.9803x over previous
#include <cuda_runtime.h>
#include <cuda_bf16.h>
#include <cstdint>

#define BATCH 4
#define SEQ   2048
#define DMODEL 1024
#define NHEAD 16
#define DK    64
#define NTOK  (BATCH*SEQ)    // 8192
#define BHTOT (BATCH*NHEAD)  // 64
#define WELEM (DMODEL*DMODEL)

// Scratch (static device globals — allocation-free per harness rules)
__device__ float g_Q[(size_t)BHTOT*SEQ*DK];
__device__ float g_K[(size_t)BHTOT*SEQ*DK];
__device__ float g_V[(size_t)BHTOT*SEQ*DK];
__device__ float g_ctx[(size_t)NTOK*DMODEL];
__device__ float g_Y[(size_t)NTOK*DMODEL];
// bf16 hi/lo scratch
__device__ __nv_bfloat16 g_ah[(size_t)NTOK*DMODEL];
__device__ __nv_bfloat16 g_al[(size_t)NTOK*DMODEL];
__device__ __nv_bfloat16 g_wh[(size_t)4*WELEM];
__device__ __nv_bfloat16 g_wl[(size_t)4*WELEM];
__device__ __nv_bfloat16 g_qh[(size_t)BHTOT*SEQ*DK];
__device__ __nv_bfloat16 g_ql[(size_t)BHTOT*SEQ*DK];
__device__ __nv_bfloat16 g_kh[(size_t)BHTOT*SEQ*DK];
__device__ __nv_bfloat16 g_kl[(size_t)BHTOT*SEQ*DK];
__device__ __nv_bfloat16 g_vth[(size_t)BHTOT*SEQ*DK];  // [bh][dk][seq]
__device__ __nv_bfloat16 g_vtl[(size_t)BHTOT*SEQ*DK];

// ---------------------------------------------------------------------------
// fp32 -> bf16 hi/lo split (optionally pre-scaled)
// ---------------------------------------------------------------------------
__global__ __launch_bounds__(256) void conv_hilo(
    const float* __restrict__ src, __nv_bfloat16* __restrict__ hi,
    __nv_bfloat16* __restrict__ lo, int n4, float scale)
{
    int i = blockIdx.x * blockDim.x + threadIdx.x;
    if (i >= n4) return;
    float4 v = *(const float4*)&src[(size_t)i * 4];
    v.x *= scale; v.y *= scale; v.z *= scale; v.w *= scale;
    __nv_bfloat16 h0 = __float2bfloat16_rn(v.x), h1 = __float2bfloat16_rn(v.y);
    __nv_bfloat16 h2 = __float2bfloat16_rn(v.z), h3 = __float2bfloat16_rn(v.w);
    __nv_bfloat162 H0(h0, h1), H1(h2, h3);
    __nv_bfloat162 L0(__float2bfloat16_rn(v.x - __bfloat162float(h0)),
                      __float2bfloat16_rn(v.y - __bfloat162float(h1)));
    __nv_bfloat162 L1(__float2bfloat16_rn(v.z - __bfloat162float(h2)),
                      __float2bfloat16_rn(v.w - __bfloat162float(h3)));
    *(uint2*)&hi[(size_t)i * 4] = make_uint2(*(uint32_t*)&H0, *(uint32_t*)&H1);
    *(uint2*)&lo[(size_t)i * 4] = make_uint2(*(uint32_t*)&L0, *(uint32_t*)&L1);
}

// ---------------------------------------------------------------------------
// V transpose + hi/lo: in [bh][s][dk] fp32 -> out [bh][dk][s] bf16 hi/lo
// ---------------------------------------------------------------------------
__global__ __launch_bounds__(256) void conv_trans(
    const float* __restrict__ src, __nv_bfloat16* __restrict__ hi,
    __nv_bfloat16* __restrict__ lo)
{
    __shared__ float t[32][33];
    const int bh = blockIdx.z;
    const int s0 = blockIdx.x * 32, d0 = blockIdx.y * 32;
    const int tx = threadIdx.x & 31, ty = threadIdx.x >> 5;   // 32 x 8
    const float* in = src + (size_t)bh * SEQ * DK;
    #pragma unroll
    for (int i = 0; i < 4; i++)
        t[ty + i * 8][tx] = in[(size_t)(s0 + ty + i * 8) * DK + d0 + tx];
    __syncthreads();
    size_t ob = (size_t)bh * DK * SEQ;
    #pragma unroll
    for (int i = 0; i < 4; i++) {
        float v = t[tx][ty + i * 8];
        __nv_bfloat16 h = __float2bfloat16_rn(v);
        size_t o = ob + (size_t)(d0 + ty + i * 8) * SEQ + s0 + tx;
        hi[o] = h;
        lo[o] = __float2bfloat16_rn(v - __bfloat162float(h));
    }
}

// ---------------------------------------------------------------------------
// mma.sync helpers
// ---------------------------------------------------------------------------
__device__ __forceinline__ void ldsm_x4(uint32_t (&r)[4], uint32_t addr) {
    asm volatile("ldmatrix.sync.aligned.m8n8.x4.shared.b16 {%0,%1,%2,%3}, [%4];"
        : "=r"(r[0]), "=r"(r[1]), "=r"(r[2]), "=r"(r[3]) : "r"(addr));
}
__device__ __forceinline__ void mma16816(float* d, const uint32_t* a, const uint32_t* b) {
    asm volatile(
        "mma.sync.aligned.m16n8k16.row.col.f32.bf16.bf16.f32 "
        "{%0,%1,%2,%3}, {%4,%5,%6,%7}, {%8,%9}, {%0,%1,%2,%3};"
        : "+f"(d[0]), "+f"(d[1]), "+f"(d[2]), "+f"(d[3])
        : "r"(a[0]), "r"(a[1]), "r"(a[2]), "r"(a[3]), "r"(b[0]), "r"(b[1]));
}
__device__ __forceinline__ uint32_t cvta_s(const void* p) {
    uint32_t a;
    asm("{ .reg .u64 t; cvta.to.shared.u64 t, %1; cvt.u32.u64 %0, t; }" : "=r"(a) : "l"(p));
    return a;
}
__device__ __forceinline__ uint32_t packbf2(float x, float y) {
    __nv_bfloat162 t(__float2bfloat16_rn(x), __float2bfloat16_rn(y));
    return *reinterpret_cast<uint32_t*>(&t);
}

// ---------------------------------------------------------------------------
// Tensor-core GEMM (bf16x3) — unchanged from round 3 (verified)
// ---------------------------------------------------------------------------
#define LDAB 40

__global__ __launch_bounds__(256, 2) void gemm_mma(
    const __nv_bfloat16* __restrict__ Ah, const __nv_bfloat16* __restrict__ Al,
    const __nv_bfloat16* __restrict__ Bh, const __nv_bfloat16* __restrict__ Bl,
    const float* __restrict__ bias, const float* __restrict__ resid,
    float* __restrict__ out, int bhsd_layout)
{
    __shared__ __nv_bfloat16 sAh[128 * LDAB], sAl[128 * LDAB];
    __shared__ __nv_bfloat16 sBh[128 * LDAB], sBl[128 * LDAB];

    const int tid = threadIdx.x;
    const int wid = tid >> 5, lane = tid & 31;
    const int bm = blockIdx.y * 128, bn = blockIdx.x * 128;
    const int wm = (wid >> 2) * 64;
    const int wn = (wid & 3) * 32;

    uint32_t sah = cvta_s(sAh), sal = cvta_s(sAl);
    uint32_t sbh = cvta_s(sBh), sbl = cvta_s(sBl);

    float acc[4][4][4];
    #pragma unroll
    for (int i = 0; i < 4; i++)
        #pragma unroll
        for (int j = 0; j < 4; j++)
            #pragma unroll
            for (int k = 0; k < 4; k++) acc[i][j][k] = 0.f;

    const int a_row = lane & 15;
    const int a_kb  = ((lane >> 4) & 1) * 16;
    const int b_row = ((lane >> 4) & 1) * 8 + (lane & 7);
    const int b_kb  = ((lane >> 3) & 1) * 16;

    for (int c = 0; c < DMODEL / 32; c++) {
        const int k0 = c * 32;
        __syncthreads();
        #pragma unroll
        for (int p = 0; p < 2; p++) {
            int idx = tid + p * 256;
            int r = idx >> 2;
            int ch = idx & 3;
            size_t ga = (size_t)(bm + r) * DMODEL + k0 + ch * 8;
            size_t gb = (size_t)(bn + r) * DMODEL + k0 + ch * 8;
            uint32_t so = (uint32_t)(r * 80 + ch * 16);
            *(uint4*)((char*)sAh + so) = *(const uint4*)&Ah[ga];
            *(uint4*)((char*)sAl + so) = *(const uint4*)&Al[ga];
            *(uint4*)((char*)sBh + so) = *(const uint4*)&Bh[gb];
            *(uint4*)((char*)sBl + so) = *(const uint4*)&Bl[gb];
        }
        __syncthreads();

        #pragma unroll
        for (int ks = 0; ks < 2; ks++) {
            const int kbase = ks * 32;
            uint32_t bh[4][2], bl[4][2];
            #pragma unroll
            for (int fp = 0; fp < 2; fp++) {
                uint32_t r4[4];
                uint32_t ba = (uint32_t)((wn + fp * 16 + b_row) * 80 + kbase + b_kb);
                ldsm_x4(r4, sbh + ba);
                bh[fp*2+0][0] = r4[0]; bh[fp*2+0][1] = r4[1];
                bh[fp*2+1][0] = r4[2]; bh[fp*2+1][1] = r4[3];
                ldsm_x4(r4, sbl + ba);
                bl[fp*2+0][0] = r4[0]; bl[fp*2+0][1] = r4[1];
                bl[fp*2+1][0] = r4[2]; bl[fp*2+1][1] = r4[3];
            }
            #pragma unroll
            for (int fm = 0; fm < 4; fm++) {
                uint32_t aa = (uint32_t)((wm + fm * 16 + a_row) * 80 + kbase + a_kb);
                uint32_t ah[4], al[4];
                ldsm_x4(ah, sah + aa);
                ldsm_x4(al, sal + aa);
                #pragma unroll
                for (int fn = 0; fn < 4; fn++) {
                    mma16816(acc[fm][fn], ah, bh[fn]);
                    mma16816(acc[fm][fn], al, bh[fn]);
                    mma16816(acc[fm][fn], ah, bl[fn]);
                }
            }
        }
    }

    const int qrow = lane >> 2;
    const int qcol = (lane & 3) * 2;
    #pragma unroll
    for (int fm = 0; fm < 4; fm++) {
        #pragma unroll
        for (int fn = 0; fn < 4; fn++) {
            int col = bn + wn + fn * 8 + qcol;
            float2 b2 = *(const float2*)&bias[col];
            #pragma unroll
            for (int h = 0; h < 2; h++) {
                int row = bm + wm + fm * 16 + qrow + h * 8;
                float2 v;
                v.x = acc[fm][fn][h * 2 + 0] + b2.x;
                v.y = acc[fm][fn][h * 2 + 1] + b2.y;
                if (resid) {
                    float2 r2 = *(const float2*)&resid[(size_t)row * DMODEL + col];
                    v.x += r2.x; v.y += r2.y;
                }
                if (bhsd_layout) {
                    int hh = col >> 6, dki = col & 63;
                    int bb = row >> 11, ss = row & 2047;
                    *(float2*)&out[(((size_t)bb * NHEAD + hh) * SEQ + ss) * DK + dki] = v;
                } else {
                    *(float2*)&out[(size_t)row * DMODEL + col] = v;
                }
            }
        }
    }
}

// ---------------------------------------------------------------------------
// Flash attention with mma.sync bf16x3.
// CTA: 128 q-rows, 8 warps (16 rows each). KV tile 64. Q frags in registers.
// smem: K hi/lo [64][72], Vt hi/lo [64][72] (144B row stride).
// ---------------------------------------------------------------------------
#define LDK 72

__global__ __launch_bounds__(256, 1) void flash_mma()
{
    __shared__ __nv_bfloat16 sKh[64 * LDK], sKl[64 * LDK];
    __shared__ __nv_bfloat16 sVh[64 * LDK], sVl[64 * LDK];

    const int tid = threadIdx.x, wid = tid >> 5, lane = tid & 31;
    const int bh = blockIdx.y;
    const int q0 = blockIdx.x * 128;

    const __nv_bfloat16* Qh = g_qh + (size_t)bh * SEQ * DK;
    const __nv_bfloat16* Ql = g_ql + (size_t)bh * SEQ * DK;
    const __nv_bfloat16* Kh = g_kh + (size_t)bh * SEQ * DK;
    const __nv_bfloat16* Kl = g_kl + (size_t)bh * SEQ * DK;
    const __nv_bfloat16* Vth = g_vth + (size_t)bh * DK * SEQ;
    const __nv_bfloat16* Vtl = g_vtl + (size_t)bh * DK * SEQ;

    uint32_t skh = cvta_s(sKh), skl = cvta_s(sKl);
    uint32_t svh = cvta_s(sVh), svl = cvta_s(sVl);

    const int a_row = lane & 15;
    const int a_kb  = ((lane >> 4) & 1) * 16;
    const int b_row = ((lane >> 4) & 1) * 8 + (lane & 7);
    const int b_kb  = ((lane >> 3) & 1) * 16;

    // ---- stage Q into registers (two 64-row halves through sK buffers) ----
    uint32_t qfh[4][4], qfl[4][4];
    #pragma unroll
    for (int half = 0; half < 2; half++) {
        #pragma unroll
        for (int p = 0; p < 2; p++) {
            int idx = tid + p * 256;
            int r = idx >> 3, ch = idx & 7;
            uint32_t so = (uint32_t)(r * 144 + ch * 16);
            size_t g = (size_t)(q0 + half * 64 + r) * DK + ch * 8;
            *(uint4*)((char*)sKh + so) = *(const uint4*)&Qh[g];
            *(uint4*)((char*)sKl + so) = *(const uint4*)&Ql[g];
        }
        __syncthreads();
        if ((wid >> 2) == half) {
            int wr = (wid & 3) * 16;
            #pragma unroll
            for (int kc = 0; kc < 4; kc++) {
                uint32_t aa = (uint32_t)((wr + a_row) * 144 + kc * 32 + a_kb);
                ldsm_x4(qfh[kc], skh + aa);
                ldsm_x4(qfl[kc], skl + aa);
            }
        }
        __syncthreads();
    }

    float m0 = -1e30f, m1 = -1e30f, l0 = 0.f, l1 = 0.f;
    float o[8][4];
    #pragma unroll
    for (int i = 0; i < 8; i++)
        #pragma unroll
        for (int j = 0; j < 4; j++) o[i][j] = 0.f;

    for (int kt = 0; kt < SEQ; kt += 64) {
        // ---- load K and Vt tiles (hi/lo) ----
        #pragma unroll
        for (int p = 0; p < 2; p++) {
            int idx = tid + p * 256;
            int r = idx >> 3, ch = idx & 7;
            uint32_t so = (uint32_t)(r * 144 + ch * 16);
            size_t gk = (size_t)(kt + r) * DK + ch * 8;
            size_t gv = (size_t)r * SEQ + kt + ch * 8;
            *(uint4*)((char*)sKh + so) = *(const uint4*)&Kh[gk];
            *(uint4*)((char*)sKl + so) = *(const uint4*)&Kl[gk];
            *(uint4*)((char*)sVh + so) = *(const uint4*)&Vth[gv];
            *(uint4*)((char*)sVl + so) = *(const uint4*)&Vtl[gv];
        }
        __syncthreads();

        // ---- S = Q K^T (bf16x3), Q pre-scaled by 1/8 ----
        float s[8][4];
        #pragma unroll
        for (int i = 0; i < 8; i++)
            #pragma unroll
            for (int j = 0; j < 4; j++) s[i][j] = 0.f;
        #pragma unroll
        for (int kc = 0; kc < 4; kc++) {
            #pragma unroll
            for (int f = 0; f < 4; f++) {
                uint32_t ba = (uint32_t)((f * 16 + b_row) * 144 + kc * 32 + b_kb);
                uint32_t kh4[4], kl4[4];
                ldsm_x4(kh4, skh + ba);
                ldsm_x4(kl4, skl + ba);
                mma16816(s[2*f+0], qfh[kc], &kh4[0]);
                mma16816(s[2*f+0], qfl[kc], &kh4[0]);
                mma16816(s[2*f+0], qfh[kc], &kl4[0]);
                mma16816(s[2*f+1], qfh[kc], &kh4[2]);
                mma16816(s[2*f+1], qfl[kc], &kh4[2]);
                mma16816(s[2*f+1], qfh[kc], &kl4[2]);
            }
        }

        // ---- online softmax (lane owns rows r and r+8; quad shares row) ----
        float rm0 = -1e30f, rm1 = -1e30f;
        #pragma unroll
        for (int j = 0; j < 8; j++) {
            rm0 = fmaxf(rm0, fmaxf(s[j][0], s[j][1]));
            rm1 = fmaxf(rm1, fmaxf(s[j][2], s[j][3]));
        }
        rm0 = fmaxf(rm0, __shfl_xor_sync(0xffffffffu, rm0, 1));
        rm0 = fmaxf(rm0, __shfl_xor_sync(0xffffffffu, rm0, 2));
        rm1 = fmaxf(rm1, __shfl_xor_sync(0xffffffffu, rm1, 1));
        rm1 = fmaxf(rm1, __shfl_xor_sync(0xffffffffu, rm1, 2));
        float mn0 = fmaxf(m0, rm0), mn1 = fmaxf(m1, rm1);
        float al0 = __expf(m0 - mn0), al1 = __expf(m1 - mn1);
        float rs0 = 0.f, rs1 = 0.f;
        #pragma unroll
        for (int j = 0; j < 8; j++) {
            s[j][0] = __expf(s[j][0] - mn0);
            s[j][1] = __expf(s[j][1] - mn0);
            s[j][2] = __expf(s[j][2] - mn1);
            s[j][3] = __expf(s[j][3] - mn1);
            rs0 += s[j][0] + s[j][1];
            rs1 += s[j][2] + s[j][3];
        }
        rs0 += __shfl_xor_sync(0xffffffffu, rs0, 1);
        rs0 += __shfl_xor_sync(0xffffffffu, rs0, 2);
        rs1 += __shfl_xor_sync(0xffffffffu, rs1, 1);
        rs1 += __shfl_xor_sync(0xffffffffu, rs1, 2);
        l0 = l0 * al0 + rs0;  l1 = l1 * al1 + rs1;
        m0 = mn0;  m1 = mn1;
        #pragma unroll
        for (int j = 0; j < 8; j++) {
            o[j][0] *= al0; o[j][1] *= al0;
            o[j][2] *= al1; o[j][3] *= al1;
        }

        // ---- P -> hi/lo A-fragments (register repack) ----
        uint32_t ph[4][4], pl[4][4];
        #pragma unroll
        for (int kc = 0; kc < 4; kc++) {
            #pragma unroll
            for (int q = 0; q < 2; q++) {
                float v0 = s[2*kc+q][0], v1 = s[2*kc+q][1];
                float v2 = s[2*kc+q][2], v3 = s[2*kc+q][3];
                uint32_t h01 = packbf2(v0, v1);
                uint32_t h23 = packbf2(v2, v3);
                __nv_bfloat162 H01 = *reinterpret_cast<__nv_bfloat162*>(&h01);
                __nv_bfloat162 H23 = *reinterpret_cast<__nv_bfloat162*>(&h23);
                ph[kc][2*q+0] = h01;
                ph[kc][2*q+1] = h23;
                pl[kc][2*q+0] = packbf2(v0 - __bfloat162float(H01.x),
                                        v1 - __bfloat162float(H01.y));
                pl[kc][2*q+1] = packbf2(v2 - __bfloat162float(H23.x),
                                        v3 - __bfloat162float(H23.y));
            }
        }

        // ---- O += P V (bf16x3), B frags from Vt [dk][key] ----
        #pragma unroll
        for (int f = 0; f < 4; f++) {
            #pragma unroll
            for (int kc = 0; kc < 4; kc++) {
                uint32_t ba = (uint32_t)((f * 16 + b_row) * 144 + kc * 32 + b_kb);
                uint32_t vh4[4], vl4[4];
                ldsm_x4(vh4, svh + ba);
                ldsm_x4(vl4, svl + ba);
                mma16816(o[2*f+0], ph[kc], &vh4[0]);
                mma16816(o[2*f+0], pl[kc], &vh4[0]);
                mma16816(o[2*f+0], ph[kc], &vl4[0]);
                mma16816(o[2*f+1], ph[kc], &vh4[2]);
                mma16816(o[2*f+1], pl[kc], &vh4[2]);
                mma16816(o[2*f+1], ph[kc], &vl4[2]);
            }
        }
        __syncthreads();   // protect smem before next tile's loads
    }

    // ---- write ctx [b][s][h*64+dk] fp32 ----
    const int b = bh >> 4, h = bh & 15;
    const int r0 = q0 + wid * 16 + (lane >> 2);
    float inv0 = 1.f / l0, inv1 = 1.f / l1;
    #pragma unroll
    for (int f = 0; f < 8; f++) {
        int col = h * DK + f * 8 + (lane & 3) * 2;
        float2 v0 = make_float2(o[f][0] * inv0, o[f][1] * inv0);
        float2 v1 = make_float2(o[f][2] * inv1, o[f][3] * inv1);
        *(float2*)&g_ctx[(size_t)(b * SEQ + r0    ) * DMODEL + col] = v0;
        *(float2*)&g_ctx[(size_t)(b * SEQ + r0 + 8) * DMODEL + col] = v1;
    }
}

// ---------------------------------------------------------------------------
// LayerNorm (unchanged)
// ---------------------------------------------------------------------------
__global__ __launch_bounds__(256) void ln_fused(
    const float* __restrict__ Y, const float* __restrict__ gamma,
    const float* __restrict__ beta, float* __restrict__ out)
{
    __shared__ float s_sum[8], s_sq[8];
    const int t = blockIdx.x;
    const int tid = threadIdx.x;
    const float* row = Y + (size_t)t * DMODEL;
    float4 v = *(const float4*)&row[tid * 4];
    float sum = v.x + v.y + v.z + v.w;
    float sq  = v.x*v.x + v.y*v.y + v.z*v.z + v.w*v.w;
    #pragma unroll
    for (int off = 16; off; off >>= 1) {
        sum += __shfl_xor_sync(0xffffffffu, sum, off);
        sq  += __shfl_xor_sync(0xffffffffu, sq,  off);
    }
    int w = tid >> 5;
    if ((tid & 31) == 0) { s_sum[w] = sum; s_sq[w] = sq; }
    __syncthreads();
    if (tid < 32) {
        sum = (tid < 8) ? s_sum[tid] : 0.f;
        sq  = (tid < 8) ? s_sq[tid]  : 0.f;
        #pragma unroll
        for (int off = 4; off; off >>= 1) {
            sum += __shfl_xor_sync(0xffffffffu, sum, off);
            sq  += __shfl_xor_sync(0xffffffffu, sq,  off);
        }
        if (tid == 0) { s_sum[0] = sum; s_sq[0] = sq; }
    }
    __syncthreads();
    float mu  = s_sum[0] * (1.f / DMODEL);
    float var = s_sq[0]  * (1.f / DMODEL) - mu * mu;
    float rstd = rsqrtf(var + 1e-5f);
    float4 g  = *(const float4*)&gamma[tid * 4];
    float4 bt = *(const float4*)&beta[tid * 4];
    float4 o4;
    o4.x = (v.x - mu) * rstd * g.x + bt.x;
    o4.y = (v.y - mu) * rstd * g.y + bt.y;
    o4.z = (v.z - mu) * rstd * g.z + bt.z;
    o4.w = (v.w - mu) * rstd * g.w + bt.w;
    *(float4*)&out[(size_t)t * DMODEL + tid * 4] = o4;
}

// ---------------------------------------------------------------------------
extern "C" void kernel_launch(void* const* d_in, const int* in_sizes, int n_in,
                              void* d_out, int out_size)
{
    const float* x     = (const float*)d_in[0];
    const float* Wq    = (const float*)d_in[1];
    const float* bq    = (const float*)d_in[2];
    const float* Wk    = (const float*)d_in[3];
    const float* bk    = (const float*)d_in[4];
    const float* Wv    = (const float*)d_in[5];
    const float* bv    = (const float*)d_in[6];
    const float* Wo    = (const float*)d_in[7];
    const float* bo    = (const float*)d_in[8];
    const float* gamma = (const float*)d_in[9];
    const float* beta  = (const float*)d_in[10];
    float* out = (float*)d_out;
    (void)in_sizes; (void)n_in; (void)out_size;

    float *gq, *gk, *gv, *gctx, *gy;
    __nv_bfloat16 *ah, *al, *wh, *wl, *qh, *ql, *kh, *kl, *vth, *vtl;
    cudaGetSymbolAddress((void**)&gq,   g_Q);
    cudaGetSymbolAddress((void**)&gk,   g_K);
    cudaGetSymbolAddress((void**)&gv,   g_V);
    cudaGetSymbolAddress((void**)&gctx, g_ctx);
    cudaGetSymbolAddress((void**)&gy,   g_Y);
    cudaGetSymbolAddress((void**)&ah,   g_ah);
    cudaGetSymbolAddress((void**)&al,   g_al);
    cudaGetSymbolAddress((void**)&wh,   g_wh);
    cudaGetSymbolAddress((void**)&wl,   g_wl);
    cudaGetSymbolAddress((void**)&qh,   g_qh);
    cudaGetSymbolAddress((void**)&ql,   g_ql);
    cudaGetSymbolAddress((void**)&kh,   g_kh);
    cudaGetSymbolAddress((void**)&kl,   g_kl);
    cudaGetSymbolAddress((void**)&vth,  g_vth);
    cudaGetSymbolAddress((void**)&vtl,  g_vtl);

    const int nx4 = NTOK * DMODEL / 4;
    const int nw4 = WELEM / 4;
    const int nqkv4 = BHTOT * SEQ * DK / 4;

    conv_hilo<<<(nx4 + 255) / 256, 256>>>(x, ah, al, nx4, 1.f);
    conv_hilo<<<(nw4 + 255) / 256, 256>>>(Wq, wh + 0*(size_t)WELEM, wl + 0*(size_t)WELEM, nw4, 1.f);
    conv_hilo<<<(nw4 + 255) / 256, 256>>>(Wk, wh + 1*(size_t)WELEM, wl + 1*(size_t)WELEM, nw4, 1.f);
    conv_hilo<<<(nw4 + 255) / 256, 256>>>(Wv, wh + 2*(size_t)WELEM, wl + 2*(size_t)WELEM, nw4, 1.f);
    conv_hilo<<<(nw4 + 255) / 256, 256>>>(Wo, wh + 3*(size_t)WELEM, wl + 3*(size_t)WELEM, nw4, 1.f);

    dim3 gg(DMODEL / 128, NTOK / 128);
    gemm_mma<<<gg, 256>>>(ah, al, wh + 0*(size_t)WELEM, wl + 0*(size_t)WELEM, bq, nullptr, gq, 1);
    gemm_mma<<<gg, 256>>>(ah, al, wh + 1*(size_t)WELEM, wl + 1*(size_t)WELEM, bk, nullptr, gk, 1);
    gemm_mma<<<gg, 256>>>(ah, al, wh + 2*(size_t)WELEM, wl + 2*(size_t)WELEM, bv, nullptr, gv, 1);

    // Q scaled by 1/sqrt(dk)=0.125 (exact power of two)
    conv_hilo<<<(nqkv4 + 255) / 256, 256>>>(gq, qh, ql, nqkv4, 0.125f);
    conv_hilo<<<(nqkv4 + 255) / 256, 256>>>(gk, kh, kl, nqkv4, 1.f);
    conv_trans<<<dim3(SEQ / 32, DK / 32, BHTOT), 256>>>(gv, vth, vtl);

    flash_mma<<<dim3(SEQ / 128, BHTOT), 256>>>();

    conv_hilo<<<(nx4 + 255) / 256, 256>>>(gctx, ah, al, nx4, 1.f);
    gemm_mma<<<gg, 256>>>(ah, al, wh + 3*(size_t)WELEM, wl + 3*(size_t)WELEM, bo, x, gy, 0);

    ln_fused<<<NTOK, 256>>>(gy, gamma, beta, out);
}

// round 6
// speedup vs baseline: 3.5586x; 1.1853x over previous
#include <cuda_runtime.h>
#include <cuda_bf16.h>
#include <cstdint>

#define BATCH 4
#define SEQ   2048
#define DMODEL 1024
#define NHEAD 16
#define DK    64
#define NTOK  (BATCH*SEQ)    // 8192
#define BHTOT (BATCH*NHEAD)  // 64
#define WELEM (DMODEL*DMODEL)

// Scratch (static device globals — allocation-free per harness rules)
__device__ float g_V[(size_t)BHTOT*SEQ*DK];
__device__ float g_Y[(size_t)NTOK*DMODEL];
// bf16 hi/lo scratch
__device__ __nv_bfloat16 g_ah[(size_t)NTOK*DMODEL];   // x hi, later ctx hi
__device__ __nv_bfloat16 g_al[(size_t)NTOK*DMODEL];
__device__ __nv_bfloat16 g_wh[(size_t)4*WELEM];
__device__ __nv_bfloat16 g_wl[(size_t)4*WELEM];
__device__ __nv_bfloat16 g_qh[(size_t)BHTOT*SEQ*DK];
__device__ __nv_bfloat16 g_ql[(size_t)BHTOT*SEQ*DK];
__device__ __nv_bfloat16 g_kh[(size_t)BHTOT*SEQ*DK];
__device__ __nv_bfloat16 g_kl[(size_t)BHTOT*SEQ*DK];
__device__ __nv_bfloat16 g_vth[(size_t)BHTOT*SEQ*DK];  // [bh][dk][seq]
__device__ __nv_bfloat16 g_vtl[(size_t)BHTOT*SEQ*DK];
// ctx hi/lo written by flash epilogue
__device__ __nv_bfloat16 g_ch[(size_t)NTOK*DMODEL];
__device__ __nv_bfloat16 g_cl[(size_t)NTOK*DMODEL];

// ---------------------------------------------------------------------------
// helpers
// ---------------------------------------------------------------------------
__device__ __forceinline__ void ldsm_x4(uint32_t (&r)[4], uint32_t addr) {
    asm volatile("ldmatrix.sync.aligned.m8n8.x4.shared.b16 {%0,%1,%2,%3}, [%4];"
        : "=r"(r[0]), "=r"(r[1]), "=r"(r[2]), "=r"(r[3]) : "r"(addr));
}
__device__ __forceinline__ void mma16816(float* d, const uint32_t* a, const uint32_t* b) {
    asm volatile(
        "mma.sync.aligned.m16n8k16.row.col.f32.bf16.bf16.f32 "
        "{%0,%1,%2,%3}, {%4,%5,%6,%7}, {%8,%9}, {%0,%1,%2,%3};"
        : "+f"(d[0]), "+f"(d[1]), "+f"(d[2]), "+f"(d[3])
        : "r"(a[0]), "r"(a[1]), "r"(a[2]), "r"(a[3]), "r"(b[0]), "r"(b[1]));
}
__device__ __forceinline__ uint32_t cvta_s(const void* p) {
    uint32_t a;
    asm("{ .reg .u64 t; cvta.to.shared.u64 t, %1; cvt.u32.u64 %0, t; }" : "=r"(a) : "l"(p));
    return a;
}
__device__ __forceinline__ uint32_t packbf2(float x, float y) {
    __nv_bfloat162 t(__float2bfloat16_rn(x), __float2bfloat16_rn(y));
    return *reinterpret_cast<uint32_t*>(&t);
}
__device__ __forceinline__ void cp16(uint32_t dst, const void* src) {
    asm volatile("cp.async.ca.shared.global [%0], [%1], 16;" :: "r"(dst), "l"(src));
}
#define CP_COMMIT()  asm volatile("cp.async.commit_group;" ::: "memory")
#define CP_WAIT(N)   asm volatile("cp.async.wait_group %0;" :: "n"(N) : "memory")

// ---------------------------------------------------------------------------
// fp32 -> bf16 hi/lo split
// ---------------------------------------------------------------------------
__global__ __launch_bounds__(256) void conv_hilo(
    const float* __restrict__ src, __nv_bfloat16* __restrict__ hi,
    __nv_bfloat16* __restrict__ lo, int n4)
{
    int i = blockIdx.x * blockDim.x + threadIdx.x;
    if (i >= n4) return;
    float4 v = *(const float4*)&src[(size_t)i * 4];
    __nv_bfloat16 h0 = __float2bfloat16_rn(v.x), h1 = __float2bfloat16_rn(v.y);
    __nv_bfloat16 h2 = __float2bfloat16_rn(v.z), h3 = __float2bfloat16_rn(v.w);
    __nv_bfloat162 H0(h0, h1), H1(h2, h3);
    __nv_bfloat162 L0(__float2bfloat16_rn(v.x - __bfloat162float(h0)),
                      __float2bfloat16_rn(v.y - __bfloat162float(h1)));
    __nv_bfloat162 L1(__float2bfloat16_rn(v.z - __bfloat162float(h2)),
                      __float2bfloat16_rn(v.w - __bfloat162float(h3)));
    *(uint2*)&hi[(size_t)i * 4] = make_uint2(*(uint32_t*)&H0, *(uint32_t*)&H1);
    *(uint2*)&lo[(size_t)i * 4] = make_uint2(*(uint32_t*)&L0, *(uint32_t*)&L1);
}

// ---------------------------------------------------------------------------
// V transpose + hi/lo: [bh][s][dk] fp32 -> [bh][dk][s] bf16 hi/lo
// ---------------------------------------------------------------------------
__global__ __launch_bounds__(256) void conv_trans(
    const float* __restrict__ src, __nv_bfloat16* __restrict__ hi,
    __nv_bfloat16* __restrict__ lo)
{
    __shared__ float t[32][33];
    const int bh = blockIdx.z;
    const int s0 = blockIdx.x * 32, d0 = blockIdx.y * 32;
    const int tx = threadIdx.x & 31, ty = threadIdx.x >> 5;
    const float* in = src + (size_t)bh * SEQ * DK;
    #pragma unroll
    for (int i = 0; i < 4; i++)
        t[ty + i * 8][tx] = in[(size_t)(s0 + ty + i * 8) * DK + d0 + tx];
    __syncthreads();
    size_t ob = (size_t)bh * DK * SEQ;
    #pragma unroll
    for (int i = 0; i < 4; i++) {
        float v = t[tx][ty + i * 8];
        __nv_bfloat16 h = __float2bfloat16_rn(v);
        size_t o = ob + (size_t)(d0 + ty + i * 8) * SEQ + s0 + tx;
        hi[o] = h;
        lo[o] = __float2bfloat16_rn(v - __bfloat162float(h));
    }
}

// ---------------------------------------------------------------------------
// Tensor-core GEMM (bf16x3) with cp.async 2-stage pipeline.
// out modes: 0 = fp32 [t][e] (+resid); 1 = fp32 [b,h,s,dk]; 2 = bf16 hi/lo
// [b,h,s,dk] scaled by `scale`.
// Stage layout (bytes): Ah 0, Al 10240, Bh 20480, Bl 30720; stage = 40960.
// ---------------------------------------------------------------------------
#define G_AH 0
#define G_AL 10240
#define G_BH 20480
#define G_BL 30720
#define GSTAGE 40960
#define GSMEM (2*GSTAGE)

__global__ __launch_bounds__(256, 2) void gemm_mma(
    const __nv_bfloat16* __restrict__ Ah, const __nv_bfloat16* __restrict__ Al,
    const __nv_bfloat16* __restrict__ Bh, const __nv_bfloat16* __restrict__ Bl,
    const float* __restrict__ bias, const float* __restrict__ resid,
    float* __restrict__ outf, __nv_bfloat16* __restrict__ outh,
    __nv_bfloat16* __restrict__ outl, float scale, int mode)
{
    extern __shared__ char dynsmem[];
    const uint32_t smem_base = cvta_s(dynsmem);
    const int tid = threadIdx.x;
    const int wid = tid >> 5, lane = tid & 31;
    const int bm = blockIdx.y * 128, bn = blockIdx.x * 128;
    const int wm = (wid >> 2) * 64;
    const int wn = (wid & 3) * 32;

    float acc[4][4][4];
    #pragma unroll
    for (int i = 0; i < 4; i++)
        #pragma unroll
        for (int j = 0; j < 4; j++)
            #pragma unroll
            for (int k = 0; k < 4; k++) acc[i][j][k] = 0.f;

    const int a_row = lane & 15;
    const int a_kb  = ((lane >> 4) & 1) * 16;
    const int b_row = ((lane >> 4) & 1) * 8 + (lane & 7);
    const int b_kb  = ((lane >> 3) & 1) * 16;

    // per-thread load slots (2 x 16B per array per chunk)
    int l_r[2], l_ch[2];
    #pragma unroll
    for (int p = 0; p < 2; p++) {
        int idx = tid + p * 256;
        l_r[p] = idx >> 2;
        l_ch[p] = idx & 3;
    }

    auto load_chunk = [&](int c, int stg) {
        const int k0 = c * 32;
        uint32_t base = smem_base + stg * GSTAGE;
        #pragma unroll
        for (int p = 0; p < 2; p++) {
            int r = l_r[p], ch = l_ch[p];
            size_t ga = (size_t)(bm + r) * DMODEL + k0 + ch * 8;
            size_t gb = (size_t)(bn + r) * DMODEL + k0 + ch * 8;
            uint32_t so = (uint32_t)(r * 80 + ch * 16);
            cp16(base + G_AH + so, Ah + ga);
            cp16(base + G_AL + so, Al + ga);
            cp16(base + G_BH + so, Bh + gb);
            cp16(base + G_BL + so, Bl + gb);
        }
        CP_COMMIT();
    };

    load_chunk(0, 0);

    for (int c = 0; c < DMODEL / 32; c++) {
        if (c + 1 < DMODEL / 32) {
            load_chunk(c + 1, (c + 1) & 1);
            CP_WAIT(1);
        } else {
            CP_WAIT(0);
        }
        __syncthreads();

        uint32_t sb = smem_base + (c & 1) * GSTAGE;
        uint32_t sah = sb + G_AH, sal = sb + G_AL;
        uint32_t sbh = sb + G_BH, sbl = sb + G_BL;

        #pragma unroll
        for (int ks = 0; ks < 2; ks++) {
            const int kbase = ks * 32;
            uint32_t bhf[4][2], blf[4][2];
            #pragma unroll
            for (int fp = 0; fp < 2; fp++) {
                uint32_t r4[4];
                uint32_t ba = (uint32_t)((wn + fp * 16 + b_row) * 80 + kbase + b_kb);
                ldsm_x4(r4, sbh + ba);
                bhf[fp*2+0][0] = r4[0]; bhf[fp*2+0][1] = r4[1];
                bhf[fp*2+1][0] = r4[2]; bhf[fp*2+1][1] = r4[3];
                ldsm_x4(r4, sbl + ba);
                blf[fp*2+0][0] = r4[0]; blf[fp*2+0][1] = r4[1];
                blf[fp*2+1][0] = r4[2]; blf[fp*2+1][1] = r4[3];
            }
            #pragma unroll
            for (int fm = 0; fm < 4; fm++) {
                uint32_t aa = (uint32_t)((wm + fm * 16 + a_row) * 80 + kbase + a_kb);
                uint32_t ahf[4], alf[4];
                ldsm_x4(ahf, sah + aa);
                ldsm_x4(alf, sal + aa);
                #pragma unroll
                for (int fn = 0; fn < 4; fn++) {
                    mma16816(acc[fm][fn], ahf, bhf[fn]);
                    mma16816(acc[fm][fn], alf, bhf[fn]);
                    mma16816(acc[fm][fn], ahf, blf[fn]);
                }
            }
        }
        __syncthreads();
    }

    // ---- epilogue ----
    const int qrow = lane >> 2;
    const int qcol = (lane & 3) * 2;
    #pragma unroll
    for (int fm = 0; fm < 4; fm++) {
        #pragma unroll
        for (int fn = 0; fn < 4; fn++) {
            int col = bn + wn + fn * 8 + qcol;
            float2 b2 = *(const float2*)&bias[col];
            #pragma unroll
            for (int h = 0; h < 2; h++) {
                int row = bm + wm + fm * 16 + qrow + h * 8;
                float vx = acc[fm][fn][h * 2 + 0] + b2.x;
                float vy = acc[fm][fn][h * 2 + 1] + b2.y;
                if (mode == 0) {
                    if (resid) {
                        float2 r2 = *(const float2*)&resid[(size_t)row * DMODEL + col];
                        vx += r2.x; vy += r2.y;
                    }
                    *(float2*)&outf[(size_t)row * DMODEL + col] = make_float2(vx, vy);
                } else {
                    int hh = col >> 6, dki = col & 63;
                    int bb = row >> 11, ss = row & 2047;
                    size_t o = (((size_t)bb * NHEAD + hh) * SEQ + ss) * DK + dki;
                    if (mode == 1) {
                        *(float2*)&outf[o] = make_float2(vx, vy);
                    } else {
                        vx *= scale; vy *= scale;
                        uint32_t hp = packbf2(vx, vy);
                        __nv_bfloat162 H = *reinterpret_cast<__nv_bfloat162*>(&hp);
                        uint32_t lp = packbf2(vx - __bfloat162float(H.x),
                                              vy - __bfloat162float(H.y));
                        *(uint32_t*)&outh[o] = hp;
                        *(uint32_t*)&outl[o] = lp;
                    }
                }
            }
        }
    }
}

// ---------------------------------------------------------------------------
// Flash attention, mma.sync bf16x3, cp.async 2-stage K/V pipeline.
// Stage layout (bytes): Kh 0, Kl 9216, Vh 18432, Vl 27648; stage = 36864.
// Epilogue writes ctx directly as bf16 hi/lo [t][dmodel].
// ---------------------------------------------------------------------------
#define F_KH 0
#define F_KL 9216
#define F_VH 18432
#define F_VL 27648
#define FSTAGE 36864
#define FSMEM (2*FSTAGE)

__global__ __launch_bounds__(256, 1) void flash_mma()
{
    extern __shared__ char dynsmem[];
    const uint32_t smem_base = cvta_s(dynsmem);
    const int tid = threadIdx.x, wid = tid >> 5, lane = tid & 31;
    const int bh = blockIdx.y;
    const int q0 = blockIdx.x * 128;

    const __nv_bfloat16* Qh = g_qh + (size_t)bh * SEQ * DK;
    const __nv_bfloat16* Ql = g_ql + (size_t)bh * SEQ * DK;
    const __nv_bfloat16* Kh = g_kh + (size_t)bh * SEQ * DK;
    const __nv_bfloat16* Kl = g_kl + (size_t)bh * SEQ * DK;
    const __nv_bfloat16* Vth = g_vth + (size_t)bh * DK * SEQ;
    const __nv_bfloat16* Vtl = g_vtl + (size_t)bh * DK * SEQ;

    const int a_row = lane & 15;
    const int a_kb  = ((lane >> 4) & 1) * 16;
    const int b_row = ((lane >> 4) & 1) * 8 + (lane & 7);
    const int b_kb  = ((lane >> 3) & 1) * 16;

    int l_r[2], l_ch[2];
    #pragma unroll
    for (int p = 0; p < 2; p++) {
        int idx = tid + p * 256;
        l_r[p] = idx >> 3;
        l_ch[p] = idx & 7;
    }

    // ---- stage Q into registers (two 64-row halves through stage-0 bufs) ----
    uint32_t qfh[4][4], qfl[4][4];
    #pragma unroll
    for (int half = 0; half < 2; half++) {
        #pragma unroll
        for (int p = 0; p < 2; p++) {
            int r = l_r[p], ch = l_ch[p];
            uint32_t so = (uint32_t)(r * 144 + ch * 16);
            size_t g = (size_t)(q0 + half * 64 + r) * DK + ch * 8;
            *(uint4*)(dynsmem + F_KH + so) = *(const uint4*)&Qh[g];
            *(uint4*)(dynsmem + F_KL + so) = *(const uint4*)&Ql[g];
        }
        __syncthreads();
        if ((wid >> 2) == half) {
            int wr = (wid & 3) * 16;
            #pragma unroll
            for (int kc = 0; kc < 4; kc++) {
                uint32_t aa = (uint32_t)((wr + a_row) * 144 + kc * 32 + a_kb);
                ldsm_x4(qfh[kc], smem_base + F_KH + aa);
                ldsm_x4(qfl[kc], smem_base + F_KL + aa);
            }
        }
        __syncthreads();
    }

    auto load_kv = [&](int kt, int stg) {
        uint32_t base = smem_base + stg * FSTAGE;
        #pragma unroll
        for (int p = 0; p < 2; p++) {
            int r = l_r[p], ch = l_ch[p];
            uint32_t so = (uint32_t)(r * 144 + ch * 16);
            size_t gk = (size_t)(kt + r) * DK + ch * 8;
            size_t gv = (size_t)r * SEQ + kt + ch * 8;
            cp16(base + F_KH + so, Kh + gk);
            cp16(base + F_KL + so, Kl + gk);
            cp16(base + F_VH + so, Vth + gv);
            cp16(base + F_VL + so, Vtl + gv);
        }
        CP_COMMIT();
    };

    float m0 = -1e30f, m1 = -1e30f, l0 = 0.f, l1 = 0.f;
    float o[8][4];
    #pragma unroll
    for (int i = 0; i < 8; i++)
        #pragma unroll
        for (int j = 0; j < 4; j++) o[i][j] = 0.f;

    load_kv(0, 0);

    for (int t = 0; t < SEQ / 64; t++) {
        if (t + 1 < SEQ / 64) {
            load_kv((t + 1) * 64, (t + 1) & 1);
            CP_WAIT(1);
        } else {
            CP_WAIT(0);
        }
        __syncthreads();

        uint32_t sb = smem_base + (t & 1) * FSTAGE;
        uint32_t skh = sb + F_KH, skl = sb + F_KL;
        uint32_t svh = sb + F_VH, svl = sb + F_VL;

        // ---- S = Q K^T (bf16x3), Q pre-scaled by 1/8 ----
        float s[8][4];
        #pragma unroll
        for (int i = 0; i < 8; i++)
            #pragma unroll
            for (int j = 0; j < 4; j++) s[i][j] = 0.f;
        #pragma unroll
        for (int kc = 0; kc < 4; kc++) {
            #pragma unroll
            for (int f = 0; f < 4; f++) {
                uint32_t ba = (uint32_t)((f * 16 + b_row) * 144 + kc * 32 + b_kb);
                uint32_t kh4[4], kl4[4];
                ldsm_x4(kh4, skh + ba);
                ldsm_x4(kl4, skl + ba);
                mma16816(s[2*f+0], qfh[kc], &kh4[0]);
                mma16816(s[2*f+0], qfl[kc], &kh4[0]);
                mma16816(s[2*f+0], qfh[kc], &kl4[0]);
                mma16816(s[2*f+1], qfh[kc], &kh4[2]);
                mma16816(s[2*f+1], qfl[kc], &kh4[2]);
                mma16816(s[2*f+1], qfh[kc], &kl4[2]);
            }
        }

        // ---- online softmax ----
        float rm0 = -1e30f, rm1 = -1e30f;
        #pragma unroll
        for (int j = 0; j < 8; j++) {
            rm0 = fmaxf(rm0, fmaxf(s[j][0], s[j][1]));
            rm1 = fmaxf(rm1, fmaxf(s[j][2], s[j][3]));
        }
        rm0 = fmaxf(rm0, __shfl_xor_sync(0xffffffffu, rm0, 1));
        rm0 = fmaxf(rm0, __shfl_xor_sync(0xffffffffu, rm0, 2));
        rm1 = fmaxf(rm1, __shfl_xor_sync(0xffffffffu, rm1, 1));
        rm1 = fmaxf(rm1, __shfl_xor_sync(0xffffffffu, rm1, 2));
        float mn0 = fmaxf(m0, rm0), mn1 = fmaxf(m1, rm1);
        float al0 = __expf(m0 - mn0), al1 = __expf(m1 - mn1);
        float rs0 = 0.f, rs1 = 0.f;
        #pragma unroll
        for (int j = 0; j < 8; j++) {
            s[j][0] = __expf(s[j][0] - mn0);
            s[j][1] = __expf(s[j][1] - mn0);
            s[j][2] = __expf(s[j][2] - mn1);
            s[j][3] = __expf(s[j][3] - mn1);
            rs0 += s[j][0] + s[j][1];
            rs1 += s[j][2] + s[j][3];
        }
        rs0 += __shfl_xor_sync(0xffffffffu, rs0, 1);
        rs0 += __shfl_xor_sync(0xffffffffu, rs0, 2);
        rs1 += __shfl_xor_sync(0xffffffffu, rs1, 1);
        rs1 += __shfl_xor_sync(0xffffffffu, rs1, 2);
        l0 = l0 * al0 + rs0;  l1 = l1 * al1 + rs1;
        m0 = mn0;  m1 = mn1;
        #pragma unroll
        for (int j = 0; j < 8; j++) {
            o[j][0] *= al0; o[j][1] *= al0;
            o[j][2] *= al1; o[j][3] *= al1;
        }

        // ---- P -> hi/lo A-fragments ----
        uint32_t ph[4][4], pl[4][4];
        #pragma unroll
        for (int kc = 0; kc < 4; kc++) {
            #pragma unroll
            for (int q = 0; q < 2; q++) {
                float v0 = s[2*kc+q][0], v1 = s[2*kc+q][1];
                float v2 = s[2*kc+q][2], v3 = s[2*kc+q][3];
                uint32_t h01 = packbf2(v0, v1);
                uint32_t h23 = packbf2(v2, v3);
                __nv_bfloat162 H01 = *reinterpret_cast<__nv_bfloat162*>(&h01);
                __nv_bfloat162 H23 = *reinterpret_cast<__nv_bfloat162*>(&h23);
                ph[kc][2*q+0] = h01;
                ph[kc][2*q+1] = h23;
                pl[kc][2*q+0] = packbf2(v0 - __bfloat162float(H01.x),
                                        v1 - __bfloat162float(H01.y));
                pl[kc][2*q+1] = packbf2(v2 - __bfloat162float(H23.x),
                                        v3 - __bfloat162float(H23.y));
            }
        }

        // ---- O += P V (bf16x3) ----
        #pragma unroll
        for (int f = 0; f < 4; f++) {
            #pragma unroll
            for (int kc = 0; kc < 4; kc++) {
                uint32_t ba = (uint32_t)((f * 16 + b_row) * 144 + kc * 32 + b_kb);
                uint32_t vh4[4], vl4[4];
                ldsm_x4(vh4, svh + ba);
                ldsm_x4(vl4, svl + ba);
                mma16816(o[2*f+0], ph[kc], &vh4[0]);
                mma16816(o[2*f+0], pl[kc], &vh4[0]);
                mma16816(o[2*f+0], ph[kc], &vl4[0]);
                mma16816(o[2*f+1], ph[kc], &vh4[2]);
                mma16816(o[2*f+1], pl[kc], &vh4[2]);
                mma16816(o[2*f+1], ph[kc], &vl4[2]);
            }
        }
        __syncthreads();
    }

    // ---- write ctx as bf16 hi/lo [t][dmodel] ----
    const int b = bh >> 4, h = bh & 15;
    const int r0 = q0 + wid * 16 + (lane >> 2);
    float inv0 = 1.f / l0, inv1 = 1.f / l1;
    #pragma unroll
    for (int f = 0; f < 8; f++) {
        int col = h * DK + f * 8 + (lane & 3) * 2;
        size_t o0 = (size_t)(b * SEQ + r0    ) * DMODEL + col;
        size_t o1 = (size_t)(b * SEQ + r0 + 8) * DMODEL + col;
        float vx0 = o[f][0] * inv0, vy0 = o[f][1] * inv0;
        float vx1 = o[f][2] * inv1, vy1 = o[f][3] * inv1;
        uint32_t hp0 = packbf2(vx0, vy0);
        __nv_bfloat162 H0 = *reinterpret_cast<__nv_bfloat162*>(&hp0);
        uint32_t lp0 = packbf2(vx0 - __bfloat162float(H0.x), vy0 - __bfloat162float(H0.y));
        uint32_t hp1 = packbf2(vx1, vy1);
        __nv_bfloat162 H1 = *reinterpret_cast<__nv_bfloat162*>(&hp1);
        uint32_t lp1 = packbf2(vx1 - __bfloat162float(H1.x), vy1 - __bfloat162float(H1.y));
        *(uint32_t*)&g_ch[o0] = hp0;
        *(uint32_t*)&g_cl[o0] = lp0;
        *(uint32_t*)&g_ch[o1] = hp1;
        *(uint32_t*)&g_cl[o1] = lp1;
    }
}

// ---------------------------------------------------------------------------
// LayerNorm
// ---------------------------------------------------------------------------
__global__ __launch_bounds__(256) void ln_fused(
    const float* __restrict__ Y, const float* __restrict__ gamma,
    const float* __restrict__ beta, float* __restrict__ out)
{
    __shared__ float s_sum[8], s_sq[8];
    const int t = blockIdx.x;
    const int tid = threadIdx.x;
    const float* row = Y + (size_t)t * DMODEL;
    float4 v = *(const float4*)&row[tid * 4];
    float sum = v.x + v.y + v.z + v.w;
    float sq  = v.x*v.x + v.y*v.y + v.z*v.z + v.w*v.w;
    #pragma unroll
    for (int off = 16; off; off >>= 1) {
        sum += __shfl_xor_sync(0xffffffffu, sum, off);
        sq  += __shfl_xor_sync(0xffffffffu, sq,  off);
    }
    int w = tid >> 5;
    if ((tid & 31) == 0) { s_sum[w] = sum; s_sq[w] = sq; }
    __syncthreads();
    if (tid < 32) {
        sum = (tid < 8) ? s_sum[tid] : 0.f;
        sq  = (tid < 8) ? s_sq[tid]  : 0.f;
        #pragma unroll
        for (int off = 4; off; off >>= 1) {
            sum += __shfl_xor_sync(0xffffffffu, sum, off);
            sq  += __shfl_xor_sync(0xffffffffu, sq,  off);
        }
        if (tid == 0) { s_sum[0] = sum; s_sq[0] = sq; }
    }
    __syncthreads();
    float mu  = s_sum[0] * (1.f / DMODEL);
    float var = s_sq[0]  * (1.f / DMODEL) - mu * mu;
    float rstd = rsqrtf(var + 1e-5f);
    float4 g  = *(const float4*)&gamma[tid * 4];
    float4 bt = *(const float4*)&beta[tid * 4];
    float4 o4;
    o4.x = (v.x - mu) * rstd * g.x + bt.x;
    o4.y = (v.y - mu) * rstd * g.y + bt.y;
    o4.z = (v.z - mu) * rstd * g.z + bt.z;
    o4.w = (v.w - mu) * rstd * g.w + bt.w;
    *(float4*)&out[(size_t)t * DMODEL + tid * 4] = o4;
}

// ---------------------------------------------------------------------------
extern "C" void kernel_launch(void* const* d_in, const int* in_sizes, int n_in,
                              void* d_out, int out_size)
{
    const float* x     = (const float*)d_in[0];
    const float* Wq    = (const float*)d_in[1];
    const float* bq    = (const float*)d_in[2];
    const float* Wk    = (const float*)d_in[3];
    const float* bk    = (const float*)d_in[4];
    const float* Wv    = (const float*)d_in[5];
    const float* bv    = (const float*)d_in[6];
    const float* Wo    = (const float*)d_in[7];
    const float* bo    = (const float*)d_in[8];
    const float* gamma = (const float*)d_in[9];
    const float* beta  = (const float*)d_in[10];
    float* out = (float*)d_out;
    (void)in_sizes; (void)n_in; (void)out_size;

    float *gv, *gy;
    __nv_bfloat16 *ah, *al, *wh, *wl, *qh, *ql, *kh, *kl, *vth, *vtl, *ch, *cl;
    cudaGetSymbolAddress((void**)&gv,   g_V);
    cudaGetSymbolAddress((void**)&gy,   g_Y);
    cudaGetSymbolAddress((void**)&ah,   g_ah);
    cudaGetSymbolAddress((void**)&al,   g_al);
    cudaGetSymbolAddress((void**)&wh,   g_wh);
    cudaGetSymbolAddress((void**)&wl,   g_wl);
    cudaGetSymbolAddress((void**)&qh,   g_qh);
    cudaGetSymbolAddress((void**)&ql,   g_ql);
    cudaGetSymbolAddress((void**)&kh,   g_kh);
    cudaGetSymbolAddress((void**)&kl,   g_kl);
    cudaGetSymbolAddress((void**)&vth,  g_vth);
    cudaGetSymbolAddress((void**)&vtl,  g_vtl);
    cudaGetSymbolAddress((void**)&ch,   g_ch);
    cudaGetSymbolAddress((void**)&cl,   g_cl);

    static bool attr_done = false;
    if (!attr_done) {
        cudaFuncSetAttribute(gemm_mma, cudaFuncAttributeMaxDynamicSharedMemorySize, GSMEM);
        cudaFuncSetAttribute(flash_mma, cudaFuncAttributeMaxDynamicSharedMemorySize, FSMEM);
        attr_done = true;
    }

    const int nx4 = NTOK * DMODEL / 4;
    const int nw4 = WELEM / 4;

    conv_hilo<<<(nx4 + 255) / 256, 256>>>(x, ah, al, nx4);
    conv_hilo<<<(nw4 + 255) / 256, 256>>>(Wq, wh + 0*(size_t)WELEM, wl + 0*(size_t)WELEM, nw4);
    conv_hilo<<<(nw4 + 255) / 256, 256>>>(Wk, wh + 1*(size_t)WELEM, wl + 1*(size_t)WELEM, nw4);
    conv_hilo<<<(nw4 + 255) / 256, 256>>>(Wv, wh + 2*(size_t)WELEM, wl + 2*(size_t)WELEM, nw4);
    conv_hilo<<<(nw4 + 255) / 256, 256>>>(Wo, wh + 3*(size_t)WELEM, wl + 3*(size_t)WELEM, nw4);

    dim3 gg(DMODEL / 128, NTOK / 128);
    // Q: bf16 hi/lo, pre-scaled by 1/sqrt(dk)=0.125
    gemm_mma<<<gg, 256, GSMEM>>>(ah, al, wh + 0*(size_t)WELEM, wl + 0*(size_t)WELEM,
                                 bq, nullptr, nullptr, qh, ql, 0.125f, 2);
    // K: bf16 hi/lo
    gemm_mma<<<gg, 256, GSMEM>>>(ah, al, wh + 1*(size_t)WELEM, wl + 1*(size_t)WELEM,
                                 bk, nullptr, nullptr, kh, kl, 1.f, 2);
    // V: fp32 bhsd (transposed by conv_trans)
    gemm_mma<<<gg, 256, GSMEM>>>(ah, al, wh + 2*(size_t)WELEM, wl + 2*(size_t)WELEM,
                                 bv, nullptr, gv, nullptr, nullptr, 1.f, 1);
    conv_trans<<<dim3(SEQ / 32, DK / 32, BHTOT), 256>>>(gv, vth, vtl);

    flash_mma<<<dim3(SEQ / 128, BHTOT), 256, FSMEM>>>();

    // out-proj: ctx (bf16 hi/lo from flash) @ Wo^T + bo + x
    gemm_mma<<<gg, 256, GSMEM>>>(ch, cl, wh + 3*(size_t)WELEM, wl + 3*(size_t)WELEM,
                                 bo, x, gy, nullptr, nullptr, 1.f, 0);

    ln_fused<<<NTOK, 256>>>(gy, gamma, beta, out);
}

// round 7
// speedup vs baseline: 4.6015x; 1.2931x over previous
#include <cuda_runtime.h>
#include <cuda_fp16.h>
#include <cstdint>

#define BATCH 4
#define SEQ   2048
#define DMODEL 1024
#define NHEAD 16
#define DK    64
#define NTOK  (BATCH*SEQ)    // 8192
#define BHTOT (BATCH*NHEAD)  // 64
#define WELEM (DMODEL*DMODEL)

// Scratch (static device globals — allocation-free per harness rules)
__device__ float g_V[(size_t)BHTOT*SEQ*DK];
__device__ float g_Y[(size_t)NTOK*DMODEL];
// fp16 scratch
__device__ __half g_ah[(size_t)NTOK*DMODEL];    // x hi
__device__ __half g_al[(size_t)NTOK*DMODEL];    // x lo
__device__ __half g_wh[(size_t)4*WELEM];        // weights, single fp16
__device__ __half g_qh[(size_t)BHTOT*SEQ*DK];
__device__ __half g_ql[(size_t)BHTOT*SEQ*DK];
__device__ __half g_kh[(size_t)BHTOT*SEQ*DK];   // K single
__device__ __half g_vth[(size_t)BHTOT*SEQ*DK];  // V^T single [bh][dk][seq]
__device__ __half g_ch[(size_t)NTOK*DMODEL];    // ctx hi
__device__ __half g_cl[(size_t)NTOK*DMODEL];    // ctx lo

// ---------------------------------------------------------------------------
// helpers
// ---------------------------------------------------------------------------
__device__ __forceinline__ void ldsm_x4(uint32_t (&r)[4], uint32_t addr) {
    asm volatile("ldmatrix.sync.aligned.m8n8.x4.shared.b16 {%0,%1,%2,%3}, [%4];"
        : "=r"(r[0]), "=r"(r[1]), "=r"(r[2]), "=r"(r[3]) : "r"(addr));
}
__device__ __forceinline__ void mma16816(float* d, const uint32_t* a, const uint32_t* b) {
    asm volatile(
        "mma.sync.aligned.m16n8k16.row.col.f32.f16.f16.f32 "
        "{%0,%1,%2,%3}, {%4,%5,%6,%7}, {%8,%9}, {%0,%1,%2,%3};"
        : "+f"(d[0]), "+f"(d[1]), "+f"(d[2]), "+f"(d[3])
        : "r"(a[0]), "r"(a[1]), "r"(a[2]), "r"(a[3]), "r"(b[0]), "r"(b[1]));
}
__device__ __forceinline__ uint32_t cvta_s(const void* p) {
    uint32_t a;
    asm("{ .reg .u64 t; cvta.to.shared.u64 t, %1; cvt.u32.u64 %0, t; }" : "=r"(a) : "l"(p));
    return a;
}
__device__ __forceinline__ uint32_t packh2(float x, float y) {
    __half2 t(__float2half_rn(x), __float2half_rn(y));
    return *reinterpret_cast<uint32_t*>(&t);
}
__device__ __forceinline__ void cp16(uint32_t dst, const void* src) {
    asm volatile("cp.async.ca.shared.global [%0], [%1], 16;" :: "r"(dst), "l"(src));
}
#define CP_COMMIT()  asm volatile("cp.async.commit_group;" ::: "memory")
#define CP_WAIT(N)   asm volatile("cp.async.wait_group %0;" :: "n"(N) : "memory")

// ---------------------------------------------------------------------------
// fp32 -> fp16 hi/lo split
// ---------------------------------------------------------------------------
__global__ __launch_bounds__(256) void conv_hilo(
    const float* __restrict__ src, __half* __restrict__ hi,
    __half* __restrict__ lo, int n4)
{
    int i = blockIdx.x * blockDim.x + threadIdx.x;
    if (i >= n4) return;
    float4 v = *(const float4*)&src[(size_t)i * 4];
    __half h0 = __float2half_rn(v.x), h1 = __float2half_rn(v.y);
    __half h2 = __float2half_rn(v.z), h3 = __float2half_rn(v.w);
    __half2 H0(h0, h1), H1(h2, h3);
    __half2 L0(__float2half_rn(v.x - __half2float(h0)),
               __float2half_rn(v.y - __half2float(h1)));
    __half2 L1(__float2half_rn(v.z - __half2float(h2)),
               __float2half_rn(v.w - __half2float(h3)));
    *(uint2*)&hi[(size_t)i * 4] = make_uint2(*(uint32_t*)&H0, *(uint32_t*)&H1);
    *(uint2*)&lo[(size_t)i * 4] = make_uint2(*(uint32_t*)&L0, *(uint32_t*)&L1);
}

// fp32 -> fp16 single (weights)
__global__ __launch_bounds__(256) void conv_f16(
    const float* __restrict__ src, __half* __restrict__ dst, int n4)
{
    int i = blockIdx.x * blockDim.x + threadIdx.x;
    if (i >= n4) return;
    float4 v = *(const float4*)&src[(size_t)i * 4];
    __half2 A(__float2half_rn(v.x), __float2half_rn(v.y));
    __half2 B(__float2half_rn(v.z), __float2half_rn(v.w));
    *(uint2*)&dst[(size_t)i * 4] = make_uint2(*(uint32_t*)&A, *(uint32_t*)&B);
}

// ---------------------------------------------------------------------------
// V transpose: [bh][s][dk] fp32 -> [bh][dk][s] fp16 single
// ---------------------------------------------------------------------------
__global__ __launch_bounds__(256) void conv_trans(
    const float* __restrict__ src, __half* __restrict__ hi)
{
    __shared__ float t[32][33];
    const int bh = blockIdx.z;
    const int s0 = blockIdx.x * 32, d0 = blockIdx.y * 32;
    const int tx = threadIdx.x & 31, ty = threadIdx.x >> 5;
    const float* in = src + (size_t)bh * SEQ * DK;
    #pragma unroll
    for (int i = 0; i < 4; i++)
        t[ty + i * 8][tx] = in[(size_t)(s0 + ty + i * 8) * DK + d0 + tx];
    __syncthreads();
    size_t ob = (size_t)bh * DK * SEQ;
    #pragma unroll
    for (int i = 0; i < 4; i++)
        hi[ob + (size_t)(d0 + ty + i * 8) * SEQ + s0 + tx] =
            __float2half_rn(t[tx][ty + i * 8]);
}

// ---------------------------------------------------------------------------
// Tensor-core GEMM (fp16 2-pass): out[t,e] = sum_d X[t,d]*W[e,d] + bias (+resid)
// A = Ah+Al fp16 hi/lo; B = single fp16.
// modes: 0 fp32 [t][e] (+resid); 1 fp32 bhsd; 2 fp16 hi/lo bhsd scaled; 3 fp16 bhsd
// Stage layout (bytes): Ah 0, Al 10240, Bh 20480; stage = 30720.
// ---------------------------------------------------------------------------
#define G_AH 0
#define G_AL 10240
#define G_BH 20480
#define GSTAGE 30720
#define GSMEM (2*GSTAGE)

__global__ __launch_bounds__(256, 2) void gemm_mma(
    const __half* __restrict__ Ah, const __half* __restrict__ Al,
    const __half* __restrict__ Bh,
    const float* __restrict__ bias, const float* __restrict__ resid,
    float* __restrict__ outf, __half* __restrict__ outh,
    __half* __restrict__ outl, float scale, int mode)
{
    extern __shared__ char dynsmem[];
    const uint32_t smem_base = cvta_s(dynsmem);
    const int tid = threadIdx.x;
    const int wid = tid >> 5, lane = tid & 31;
    const int bm = blockIdx.y * 128, bn = blockIdx.x * 128;
    const int wm = (wid >> 2) * 64;
    const int wn = (wid & 3) * 32;

    float acc[4][4][4];
    #pragma unroll
    for (int i = 0; i < 4; i++)
        #pragma unroll
        for (int j = 0; j < 4; j++)
            #pragma unroll
            for (int k = 0; k < 4; k++) acc[i][j][k] = 0.f;

    const int a_row = lane & 15;
    const int a_kb  = ((lane >> 4) & 1) * 16;
    const int b_row = ((lane >> 4) & 1) * 8 + (lane & 7);
    const int b_kb  = ((lane >> 3) & 1) * 16;

    int l_r[2], l_ch[2];
    #pragma unroll
    for (int p = 0; p < 2; p++) {
        int idx = tid + p * 256;
        l_r[p] = idx >> 2;
        l_ch[p] = idx & 3;
    }

    auto load_chunk = [&](int c, int stg) {
        const int k0 = c * 32;
        uint32_t base = smem_base + stg * GSTAGE;
        #pragma unroll
        for (int p = 0; p < 2; p++) {
            int r = l_r[p], ch = l_ch[p];
            size_t ga = (size_t)(bm + r) * DMODEL + k0 + ch * 8;
            size_t gb = (size_t)(bn + r) * DMODEL + k0 + ch * 8;
            uint32_t so = (uint32_t)(r * 80 + ch * 16);
            cp16(base + G_AH + so, Ah + ga);
            cp16(base + G_AL + so, Al + ga);
            cp16(base + G_BH + so, Bh + gb);
        }
        CP_COMMIT();
    };

    load_chunk(0, 0);

    for (int c = 0; c < DMODEL / 32; c++) {
        if (c + 1 < DMODEL / 32) {
            load_chunk(c + 1, (c + 1) & 1);
            CP_WAIT(1);
        } else {
            CP_WAIT(0);
        }
        __syncthreads();

        uint32_t sb = smem_base + (c & 1) * GSTAGE;
        uint32_t sah = sb + G_AH, sal = sb + G_AL, sbh = sb + G_BH;

        #pragma unroll
        for (int ks = 0; ks < 2; ks++) {
            const int kbase = ks * 32;
            uint32_t bhf[4][2];
            #pragma unroll
            for (int fp = 0; fp < 2; fp++) {
                uint32_t r4[4];
                uint32_t ba = (uint32_t)((wn + fp * 16 + b_row) * 80 + kbase + b_kb);
                ldsm_x4(r4, sbh + ba);
                bhf[fp*2+0][0] = r4[0]; bhf[fp*2+0][1] = r4[1];
                bhf[fp*2+1][0] = r4[2]; bhf[fp*2+1][1] = r4[3];
            }
            #pragma unroll
            for (int fm = 0; fm < 4; fm++) {
                uint32_t aa = (uint32_t)((wm + fm * 16 + a_row) * 80 + kbase + a_kb);
                uint32_t ahf[4], alf[4];
                ldsm_x4(ahf, sah + aa);
                ldsm_x4(alf, sal + aa);
                #pragma unroll
                for (int fn = 0; fn < 4; fn++) {
                    mma16816(acc[fm][fn], ahf, bhf[fn]);
                    mma16816(acc[fm][fn], alf, bhf[fn]);
                }
            }
        }
        __syncthreads();
    }

    // ---- epilogue ----
    const int qrow = lane >> 2;
    const int qcol = (lane & 3) * 2;
    #pragma unroll
    for (int fm = 0; fm < 4; fm++) {
        #pragma unroll
        for (int fn = 0; fn < 4; fn++) {
            int col = bn + wn + fn * 8 + qcol;
            float2 b2 = *(const float2*)&bias[col];
            #pragma unroll
            for (int h = 0; h < 2; h++) {
                int row = bm + wm + fm * 16 + qrow + h * 8;
                float vx = acc[fm][fn][h * 2 + 0] + b2.x;
                float vy = acc[fm][fn][h * 2 + 1] + b2.y;
                if (mode == 0) {
                    if (resid) {
                        float2 r2 = *(const float2*)&resid[(size_t)row * DMODEL + col];
                        vx += r2.x; vy += r2.y;
                    }
                    *(float2*)&outf[(size_t)row * DMODEL + col] = make_float2(vx, vy);
                } else {
                    int hh = col >> 6, dki = col & 63;
                    int bb = row >> 11, ss = row & 2047;
                    size_t o = (((size_t)bb * NHEAD + hh) * SEQ + ss) * DK + dki;
                    if (mode == 1) {
                        *(float2*)&outf[o] = make_float2(vx, vy);
                    } else if (mode == 3) {
                        *(uint32_t*)&outh[o] = packh2(vx, vy);
                    } else {
                        vx *= scale; vy *= scale;
                        uint32_t hp = packh2(vx, vy);
                        __half2 H = *reinterpret_cast<__half2*>(&hp);
                        uint32_t lp = packh2(vx - __half2float(H.x),
                                             vy - __half2float(H.y));
                        *(uint32_t*)&outh[o] = hp;
                        *(uint32_t*)&outl[o] = lp;
                    }
                }
            }
        }
    }
}

// ---------------------------------------------------------------------------
// Flash attention, fp16 2-pass, cp.async 2-stage K/V pipeline.
// Q (hi/lo) register-resident A operand; K, V^T single fp16 B operands;
// P split hi/lo in registers.
// Stage layout (bytes): Kh 0, Vh 9216; stage = 18432.
// ---------------------------------------------------------------------------
#define F_KH 0
#define F_VH 9216
#define FSTAGE 18432
#define FSMEM (2*FSTAGE)

__global__ __launch_bounds__(256, 1) void flash_mma()
{
    extern __shared__ char dynsmem[];
    const uint32_t smem_base = cvta_s(dynsmem);
    const int tid = threadIdx.x, wid = tid >> 5, lane = tid & 31;
    const int bh = blockIdx.y;
    const int q0 = blockIdx.x * 128;

    const __half* Qh = g_qh + (size_t)bh * SEQ * DK;
    const __half* Ql = g_ql + (size_t)bh * SEQ * DK;
    const __half* Kh = g_kh + (size_t)bh * SEQ * DK;
    const __half* Vth = g_vth + (size_t)bh * DK * SEQ;

    const int a_row = lane & 15;
    const int a_kb  = ((lane >> 4) & 1) * 16;
    const int b_row = ((lane >> 4) & 1) * 8 + (lane & 7);
    const int b_kb  = ((lane >> 3) & 1) * 16;

    int l_r[2], l_ch[2];
    #pragma unroll
    for (int p = 0; p < 2; p++) {
        int idx = tid + p * 256;
        l_r[p] = idx >> 3;
        l_ch[p] = idx & 7;
    }

    // ---- stage Q into registers (two 64-row halves through stage-0 bufs) ----
    uint32_t qfh[4][4], qfl[4][4];
    #pragma unroll
    for (int half = 0; half < 2; half++) {
        #pragma unroll
        for (int p = 0; p < 2; p++) {
            int r = l_r[p], ch = l_ch[p];
            uint32_t so = (uint32_t)(r * 144 + ch * 16);
            size_t g = (size_t)(q0 + half * 64 + r) * DK + ch * 8;
            *(uint4*)(dynsmem + F_KH + so) = *(const uint4*)&Qh[g];
            *(uint4*)(dynsmem + F_VH + so) = *(const uint4*)&Ql[g];
        }
        __syncthreads();
        if ((wid >> 2) == half) {
            int wr = (wid & 3) * 16;
            #pragma unroll
            for (int kc = 0; kc < 4; kc++) {
                uint32_t aa = (uint32_t)((wr + a_row) * 144 + kc * 32 + a_kb);
                ldsm_x4(qfh[kc], smem_base + F_KH + aa);
                ldsm_x4(qfl[kc], smem_base + F_VH + aa);
            }
        }
        __syncthreads();
    }

    auto load_kv = [&](int kt, int stg) {
        uint32_t base = smem_base + stg * FSTAGE;
        #pragma unroll
        for (int p = 0; p < 2; p++) {
            int r = l_r[p], ch = l_ch[p];
            uint32_t so = (uint32_t)(r * 144 + ch * 16);
            size_t gk = (size_t)(kt + r) * DK + ch * 8;
            size_t gv = (size_t)r * SEQ + kt + ch * 8;
            cp16(base + F_KH + so, Kh + gk);
            cp16(base + F_VH + so, Vth + gv);
        }
        CP_COMMIT();
    };

    float m0 = -1e30f, m1 = -1e30f, l0 = 0.f, l1 = 0.f;
    float o[8][4];
    #pragma unroll
    for (int i = 0; i < 8; i++)
        #pragma unroll
        for (int j = 0; j < 4; j++) o[i][j] = 0.f;

    load_kv(0, 0);

    for (int t = 0; t < SEQ / 64; t++) {
        if (t + 1 < SEQ / 64) {
            load_kv((t + 1) * 64, (t + 1) & 1);
            CP_WAIT(1);
        } else {
            CP_WAIT(0);
        }
        __syncthreads();

        uint32_t sb = smem_base + (t & 1) * FSTAGE;
        uint32_t skh = sb + F_KH, svh = sb + F_VH;

        // ---- S = Q K^T (2-pass), Q pre-scaled by 1/8 ----
        float s[8][4];
        #pragma unroll
        for (int i = 0; i < 8; i++)
            #pragma unroll
            for (int j = 0; j < 4; j++) s[i][j] = 0.f;
        #pragma unroll
        for (int kc = 0; kc < 4; kc++) {
            #pragma unroll
            for (int f = 0; f < 4; f++) {
                uint32_t ba = (uint32_t)((f * 16 + b_row) * 144 + kc * 32 + b_kb);
                uint32_t kh4[4];
                ldsm_x4(kh4, skh + ba);
                mma16816(s[2*f+0], qfh[kc], &kh4[0]);
                mma16816(s[2*f+0], qfl[kc], &kh4[0]);
                mma16816(s[2*f+1], qfh[kc], &kh4[2]);
                mma16816(s[2*f+1], qfl[kc], &kh4[2]);
            }
        }

        // ---- online softmax ----
        float rm0 = -1e30f, rm1 = -1e30f;
        #pragma unroll
        for (int j = 0; j < 8; j++) {
            rm0 = fmaxf(rm0, fmaxf(s[j][0], s[j][1]));
            rm1 = fmaxf(rm1, fmaxf(s[j][2], s[j][3]));
        }
        rm0 = fmaxf(rm0, __shfl_xor_sync(0xffffffffu, rm0, 1));
        rm0 = fmaxf(rm0, __shfl_xor_sync(0xffffffffu, rm0, 2));
        rm1 = fmaxf(rm1, __shfl_xor_sync(0xffffffffu, rm1, 1));
        rm1 = fmaxf(rm1, __shfl_xor_sync(0xffffffffu, rm1, 2));
        float mn0 = fmaxf(m0, rm0), mn1 = fmaxf(m1, rm1);
        float al0 = __expf(m0 - mn0), al1 = __expf(m1 - mn1);
        float rs0 = 0.f, rs1 = 0.f;
        #pragma unroll
        for (int j = 0; j < 8; j++) {
            s[j][0] = __expf(s[j][0] - mn0);
            s[j][1] = __expf(s[j][1] - mn0);
            s[j][2] = __expf(s[j][2] - mn1);
            s[j][3] = __expf(s[j][3] - mn1);
            rs0 += s[j][0] + s[j][1];
            rs1 += s[j][2] + s[j][3];
        }
        rs0 += __shfl_xor_sync(0xffffffffu, rs0, 1);
        rs0 += __shfl_xor_sync(0xffffffffu, rs0, 2);
        rs1 += __shfl_xor_sync(0xffffffffu, rs1, 1);
        rs1 += __shfl_xor_sync(0xffffffffu, rs1, 2);
        l0 = l0 * al0 + rs0;  l1 = l1 * al1 + rs1;
        m0 = mn0;  m1 = mn1;
        #pragma unroll
        for (int j = 0; j < 8; j++) {
            o[j][0] *= al0; o[j][1] *= al0;
            o[j][2] *= al1; o[j][3] *= al1;
        }

        // ---- P -> hi/lo A-fragments (register repack) ----
        uint32_t ph[4][4], pl[4][4];
        #pragma unroll
        for (int kc = 0; kc < 4; kc++) {
            #pragma unroll
            for (int q = 0; q < 2; q++) {
                float v0 = s[2*kc+q][0], v1 = s[2*kc+q][1];
                float v2 = s[2*kc+q][2], v3 = s[2*kc+q][3];
                uint32_t h01 = packh2(v0, v1);
                uint32_t h23 = packh2(v2, v3);
                __half2 H01 = *reinterpret_cast<__half2*>(&h01);
                __half2 H23 = *reinterpret_cast<__half2*>(&h23);
                ph[kc][2*q+0] = h01;
                ph[kc][2*q+1] = h23;
                pl[kc][2*q+0] = packh2(v0 - __half2float(H01.x),
                                       v1 - __half2float(H01.y));
                pl[kc][2*q+1] = packh2(v2 - __half2float(H23.x),
                                       v3 - __half2float(H23.y));
            }
        }

        // ---- O += P V (2-pass) ----
        #pragma unroll
        for (int f = 0; f < 4; f++) {
            #pragma unroll
            for (int kc = 0; kc < 4; kc++) {
                uint32_t ba = (uint32_t)((f * 16 + b_row) * 144 + kc * 32 + b_kb);
                uint32_t vh4[4];
                ldsm_x4(vh4, svh + ba);
                mma16816(o[2*f+0], ph[kc], &vh4[0]);
                mma16816(o[2*f+0], pl[kc], &vh4[0]);
                mma16816(o[2*f+1], ph[kc], &vh4[2]);
                mma16816(o[2*f+1], pl[kc], &vh4[2]);
            }
        }
        __syncthreads();
    }

    // ---- write ctx as fp16 hi/lo [t][dmodel] ----
    const int b = bh >> 4, h = bh & 15;
    const int r0 = q0 + wid * 16 + (lane >> 2);
    float inv0 = 1.f / l0, inv1 = 1.f / l1;
    #pragma unroll
    for (int f = 0; f < 8; f++) {
        int col = h * DK + f * 8 + (lane & 3) * 2;
        size_t o0 = (size_t)(b * SEQ + r0    ) * DMODEL + col;
        size_t o1 = (size_t)(b * SEQ + r0 + 8) * DMODEL + col;
        float vx0 = o[f][0] * inv0, vy0 = o[f][1] * inv0;
        float vx1 = o[f][2] * inv1, vy1 = o[f][3] * inv1;
        uint32_t hp0 = packh2(vx0, vy0);
        __half2 H0 = *reinterpret_cast<__half2*>(&hp0);
        uint32_t lp0 = packh2(vx0 - __half2float(H0.x), vy0 - __half2float(H0.y));
        uint32_t hp1 = packh2(vx1, vy1);
        __half2 H1 = *reinterpret_cast<__half2*>(&hp1);
        uint32_t lp1 = packh2(vx1 - __half2float(H1.x), vy1 - __half2float(H1.y));
        *(uint32_t*)&g_ch[o0] = hp0;
        *(uint32_t*)&g_cl[o0] = lp0;
        *(uint32_t*)&g_ch[o1] = hp1;
        *(uint32_t*)&g_cl[o1] = lp1;
    }
}

// ---------------------------------------------------------------------------
// LayerNorm
// ---------------------------------------------------------------------------
__global__ __launch_bounds__(256) void ln_fused(
    const float* __restrict__ Y, const float* __restrict__ gamma,
    const float* __restrict__ beta, float* __restrict__ out)
{
    __shared__ float s_sum[8], s_sq[8];
    const int t = blockIdx.x;
    const int tid = threadIdx.x;
    const float* row = Y + (size_t)t * DMODEL;
    float4 v = *(const float4*)&row[tid * 4];
    float sum = v.x + v.y + v.z + v.w;
    float sq  = v.x*v.x + v.y*v.y + v.z*v.z + v.w*v.w;
    #pragma unroll
    for (int off = 16; off; off >>= 1) {
        sum += __shfl_xor_sync(0xffffffffu, sum, off);
        sq  += __shfl_xor_sync(0xffffffffu, sq,  off);
    }
    int w = tid >> 5;
    if ((tid & 31) == 0) { s_sum[w] = sum; s_sq[w] = sq; }
    __syncthreads();
    if (tid < 32) {
        sum = (tid < 8) ? s_sum[tid] : 0.f;
        sq  = (tid < 8) ? s_sq[tid]  : 0.f;
        #pragma unroll
        for (int off = 4; off; off >>= 1) {
            sum += __shfl_xor_sync(0xffffffffu, sum, off);
            sq  += __shfl_xor_sync(0xffffffffu, sq,  off);
        }
        if (tid == 0) { s_sum[0] = sum; s_sq[0] = sq; }
    }
    __syncthreads();
    float mu  = s_sum[0] * (1.f / DMODEL);
    float var = s_sq[0]  * (1.f / DMODEL) - mu * mu;
    float rstd = rsqrtf(var + 1e-5f);
    float4 g  = *(const float4*)&gamma[tid * 4];
    float4 bt = *(const float4*)&beta[tid * 4];
    float4 o4;
    o4.x = (v.x - mu) * rstd * g.x + bt.x;
    o4.y = (v.y - mu) * rstd * g.y + bt.y;
    o4.z = (v.z - mu) * rstd * g.z + bt.z;
    o4.w = (v.w - mu) * rstd * g.w + bt.w;
    *(float4*)&out[(size_t)t * DMODEL + tid * 4] = o4;
}

// ---------------------------------------------------------------------------
extern "C" void kernel_launch(void* const* d_in, const int* in_sizes, int n_in,
                              void* d_out, int out_size)
{
    const float* x     = (const float*)d_in[0];
    const float* Wq    = (const float*)d_in[1];
    const float* bq    = (const float*)d_in[2];
    const float* Wk    = (const float*)d_in[3];
    const float* bk    = (const float*)d_in[4];
    const float* Wv    = (const float*)d_in[5];
    const float* bv    = (const float*)d_in[6];
    const float* Wo    = (const float*)d_in[7];
    const float* bo    = (const float*)d_in[8];
    const float* gamma = (const float*)d_in[9];
    const float* beta  = (const float*)d_in[10];
    float* out = (float*)d_out;
    (void)in_sizes; (void)n_in; (void)out_size;

    float *gv, *gy;
    __half *ah, *al, *wh, *qh, *ql, *kh, *vth, *ch, *cl;
    cudaGetSymbolAddress((void**)&gv,   g_V);
    cudaGetSymbolAddress((void**)&gy,   g_Y);
    cudaGetSymbolAddress((void**)&ah,   g_ah);
    cudaGetSymbolAddress((void**)&al,   g_al);
    cudaGetSymbolAddress((void**)&wh,   g_wh);
    cudaGetSymbolAddress((void**)&qh,   g_qh);
    cudaGetSymbolAddress((void**)&ql,   g_ql);
    cudaGetSymbolAddress((void**)&kh,   g_kh);
    cudaGetSymbolAddress((void**)&vth,  g_vth);
    cudaGetSymbolAddress((void**)&ch,   g_ch);
    cudaGetSymbolAddress((void**)&cl,   g_cl);

    static bool attr_done = false;
    if (!attr_done) {
        cudaFuncSetAttribute(gemm_mma, cudaFuncAttributeMaxDynamicSharedMemorySize, GSMEM);
        cudaFuncSetAttribute(flash_mma, cudaFuncAttributeMaxDynamicSharedMemorySize, FSMEM);
        attr_done = true;
    }

    const int nx4 = NTOK * DMODEL / 4;
    const int nw4 = WELEM / 4;

    conv_hilo<<<(nx4 + 255) / 256, 256>>>(x, ah, al, nx4);
    conv_f16<<<(nw4 + 255) / 256, 256>>>(Wq, wh + 0*(size_t)WELEM, nw4);
    conv_f16<<<(nw4 + 255) / 256, 256>>>(Wk, wh + 1*(size_t)WELEM, nw4);
    conv_f16<<<(nw4 + 255) / 256, 256>>>(Wv, wh + 2*(size_t)WELEM, nw4);
    conv_f16<<<(nw4 + 255) / 256, 256>>>(Wo, wh + 3*(size_t)WELEM, nw4);

    dim3 gg(DMODEL / 128, NTOK / 128);
    // Q: fp16 hi/lo, pre-scaled by 1/sqrt(dk)=0.125
    gemm_mma<<<gg, 256, GSMEM>>>(ah, al, wh + 0*(size_t)WELEM,
                                 bq, nullptr, nullptr, qh, ql, 0.125f, 2);
    // K: fp16 single
    gemm_mma<<<gg, 256, GSMEM>>>(ah, al, wh + 1*(size_t)WELEM,
                                 bk, nullptr, nullptr, kh, nullptr, 1.f, 3);
    // V: fp32 bhsd -> transpose to fp16 single
    gemm_mma<<<gg, 256, GSMEM>>>(ah, al, wh + 2*(size_t)WELEM,
                                 bv, nullptr, gv, nullptr, nullptr, 1.f, 1);
    conv_trans<<<dim3(SEQ / 32, DK / 32, BHTOT), 256>>>(gv, vth);

    flash_mma<<<dim3(SEQ / 128, BHTOT), 256, FSMEM>>>();

    // out-proj: ctx (fp16 hi/lo) @ Wo^T + bo + x
    gemm_mma<<<gg, 256, GSMEM>>>(ch, cl, wh + 3*(size_t)WELEM,
                                 bo, x, gy, nullptr, nullptr, 1.f, 0);

    ln_fused<<<NTOK, 256>>>(gy, gamma, beta, out);
}

// round 8
// speedup vs baseline: 8.3444x; 1.8134x over previous
#include <cuda_runtime.h>
#include <cuda_fp16.h>
#include <cstdint>

#define BATCH 4
#define SEQ   2048
#define DMODEL 1024
#define NHEAD 16
#define DK    64
#define NTOK  (BATCH*SEQ)    // 8192
#define BHTOT (BATCH*NHEAD)  // 64
#define WELEM (DMODEL*DMODEL)

// Scratch (static device globals — allocation-free per harness rules)
__device__ float  g_Y[(size_t)NTOK*DMODEL];
__device__ __half g_x16[(size_t)NTOK*DMODEL];
__device__ __half g_w16[(size_t)4*WELEM];
__device__ __half g_q[(size_t)BHTOT*SEQ*DK];    // pre-scaled by 0.125
__device__ __half g_k[(size_t)BHTOT*SEQ*DK];
__device__ __half g_vs[(size_t)BHTOT*SEQ*DK];   // V [bh][s][dk]
__device__ __half g_vt[(size_t)BHTOT*SEQ*DK];   // V^T [bh][dk][s]
__device__ __half g_c[(size_t)NTOK*DMODEL];     // ctx fp16

// ---------------------------------------------------------------------------
// helpers
// ---------------------------------------------------------------------------
__device__ __forceinline__ void ldsm_x4(uint32_t (&r)[4], uint32_t addr) {
    asm volatile("ldmatrix.sync.aligned.m8n8.x4.shared.b16 {%0,%1,%2,%3}, [%4];"
        : "=r"(r[0]), "=r"(r[1]), "=r"(r[2]), "=r"(r[3]) : "r"(addr));
}
__device__ __forceinline__ void mma16816(float* d, const uint32_t* a, const uint32_t* b) {
    asm volatile(
        "mma.sync.aligned.m16n8k16.row.col.f32.f16.f16.f32 "
        "{%0,%1,%2,%3}, {%4,%5,%6,%7}, {%8,%9}, {%0,%1,%2,%3};"
        : "+f"(d[0]), "+f"(d[1]), "+f"(d[2]), "+f"(d[3])
        : "r"(a[0]), "r"(a[1]), "r"(a[2]), "r"(a[3]), "r"(b[0]), "r"(b[1]));
}
__device__ __forceinline__ uint32_t cvta_s(const void* p) {
    uint32_t a;
    asm("{ .reg .u64 t; cvta.to.shared.u64 t, %1; cvt.u32.u64 %0, t; }" : "=r"(a) : "l"(p));
    return a;
}
__device__ __forceinline__ uint32_t packh2(float x, float y) {
    __half2 t(__float2half_rn(x), __float2half_rn(y));
    return *reinterpret_cast<uint32_t*>(&t);
}
__device__ __forceinline__ void cp16(uint32_t dst, const void* src) {
    asm volatile("cp.async.ca.shared.global [%0], [%1], 16;" :: "r"(dst), "l"(src));
}
#define CP_COMMIT()  asm volatile("cp.async.commit_group;" ::: "memory")
#define CP_WAIT(N)   asm volatile("cp.async.wait_group %0;" :: "n"(N) : "memory")

// ---------------------------------------------------------------------------
// fp32 -> fp16
// ---------------------------------------------------------------------------
__global__ __launch_bounds__(256) void conv_f16(
    const float* __restrict__ src, __half* __restrict__ dst, int n4)
{
    int i = blockIdx.x * blockDim.x + threadIdx.x;
    if (i >= n4) return;
    float4 v = *(const float4*)&src[(size_t)i * 4];
    __half2 A(__float2half_rn(v.x), __float2half_rn(v.y));
    __half2 B(__float2half_rn(v.z), __float2half_rn(v.w));
    *(uint2*)&dst[(size_t)i * 4] = make_uint2(*(uint32_t*)&A, *(uint32_t*)&B);
}

// ---------------------------------------------------------------------------
// V transpose fp16: [bh][s][dk] -> [bh][dk][s]
// ---------------------------------------------------------------------------
__global__ __launch_bounds__(256) void conv_trans(
    const __half* __restrict__ src, __half* __restrict__ dst)
{
    __shared__ __half t[32][34];
    const int bh = blockIdx.z;
    const int s0 = blockIdx.x * 32, d0 = blockIdx.y * 32;
    const int tx = threadIdx.x & 31, ty = threadIdx.x >> 5;
    const __half* in = src + (size_t)bh * SEQ * DK;
    #pragma unroll
    for (int i = 0; i < 4; i++)
        t[ty + i * 8][tx] = in[(size_t)(s0 + ty + i * 8) * DK + d0 + tx];
    __syncthreads();
    size_t ob = (size_t)bh * DK * SEQ;
    #pragma unroll
    for (int i = 0; i < 4; i++)
        dst[ob + (size_t)(d0 + ty + i * 8) * SEQ + s0 + tx] = t[tx][ty + i * 8];
}

// ---------------------------------------------------------------------------
// GEMM core (fp16 single-pass): acc[t,e] = sum_d A[t,d]*B[e,d]
// CTA 128x128, K-chunk 32, cp.async 2-stage. smem row stride 80B.
// ---------------------------------------------------------------------------
#define G_A 0
#define G_B 10240
#define GSTAGE 20480
#define GSMEM (2*GSTAGE)

__device__ __forceinline__ void gemm_core(
    const __half* __restrict__ A, const __half* __restrict__ B,
    char* dynsmem, int tid, int wid, int lane, int bm, int bn,
    float (&acc)[4][4][4])
{
    const uint32_t smem_base = cvta_s(dynsmem);
    const int wm = (wid >> 2) * 64, wn = (wid & 3) * 32;
    const int a_row = lane & 15;
    const int a_kb  = ((lane >> 4) & 1) * 16;
    const int b_row = ((lane >> 4) & 1) * 8 + (lane & 7);
    const int b_kb  = ((lane >> 3) & 1) * 16;

    int l_r[2], l_ch[2];
    #pragma unroll
    for (int p = 0; p < 2; p++) {
        int idx = tid + p * 256;
        l_r[p] = idx >> 2;
        l_ch[p] = idx & 3;
    }

    auto load_chunk = [&](int c, int stg) {
        const int k0 = c * 32;
        uint32_t base = smem_base + stg * GSTAGE;
        #pragma unroll
        for (int p = 0; p < 2; p++) {
            int r = l_r[p], ch = l_ch[p];
            uint32_t so = (uint32_t)(r * 80 + ch * 16);
            cp16(base + G_A + so, A + (size_t)(bm + r) * DMODEL + k0 + ch * 8);
            cp16(base + G_B + so, B + (size_t)(bn + r) * DMODEL + k0 + ch * 8);
        }
        CP_COMMIT();
    };

    load_chunk(0, 0);

    for (int c = 0; c < DMODEL / 32; c++) {
        if (c + 1 < DMODEL / 32) {
            load_chunk(c + 1, (c + 1) & 1);
            CP_WAIT(1);
        } else {
            CP_WAIT(0);
        }
        __syncthreads();

        uint32_t sb = smem_base + (c & 1) * GSTAGE;
        uint32_t sa = sb + G_A, sbh = sb + G_B;

        #pragma unroll
        for (int ks = 0; ks < 2; ks++) {
            const int kbase = ks * 32;
            uint32_t bhf[4][2];
            #pragma unroll
            for (int fp = 0; fp < 2; fp++) {
                uint32_t r4[4];
                uint32_t ba = (uint32_t)((wn + fp * 16 + b_row) * 80 + kbase + b_kb);
                ldsm_x4(r4, sbh + ba);
                bhf[fp*2+0][0] = r4[0]; bhf[fp*2+0][1] = r4[1];
                bhf[fp*2+1][0] = r4[2]; bhf[fp*2+1][1] = r4[3];
            }
            #pragma unroll
            for (int fm = 0; fm < 4; fm++) {
                uint32_t aa = (uint32_t)((wm + fm * 16 + a_row) * 80 + kbase + a_kb);
                uint32_t af[4];
                ldsm_x4(af, sa + aa);
                #pragma unroll
                for (int fn = 0; fn < 4; fn++)
                    mma16816(acc[fm][fn], af, bhf[fn]);
            }
        }
        __syncthreads();
    }
}

// ---------------------------------------------------------------------------
// Merged QKV projection: grid.x = 24 (3 weights x 8 n-tiles), grid.y = 64.
// Writes fp16 [b,h,s,dk]; Q scaled by 0.125.
// ---------------------------------------------------------------------------
__global__ __launch_bounds__(256, 2) void gemm_qkv(
    const __half* __restrict__ X, const __half* __restrict__ W,
    const float* __restrict__ bq, const float* __restrict__ bk,
    const float* __restrict__ bv,
    __half* __restrict__ outq, __half* __restrict__ outk,
    __half* __restrict__ outv)
{
    extern __shared__ char dynsmem[];
    const int tid = threadIdx.x, wid = tid >> 5, lane = tid & 31;
    const int which = blockIdx.x >> 3;
    const int bn = (blockIdx.x & 7) * 128;
    const int bm = blockIdx.y * 128;

    const __half* B = W + (size_t)which * WELEM;
    const float* bias = (which == 0) ? bq : (which == 1) ? bk : bv;
    __half* outh = (which == 0) ? outq : (which == 1) ? outk : outv;
    const float scale = (which == 0) ? 0.125f : 1.f;

    float acc[4][4][4];
    #pragma unroll
    for (int i = 0; i < 4; i++)
        #pragma unroll
        for (int j = 0; j < 4; j++)
            #pragma unroll
            for (int k = 0; k < 4; k++) acc[i][j][k] = 0.f;

    gemm_core(X, B, dynsmem, tid, wid, lane, bm, bn, acc);

    const int wm = (wid >> 2) * 64, wn = (wid & 3) * 32;
    const int qrow = lane >> 2, qcol = (lane & 3) * 2;
    #pragma unroll
    for (int fm = 0; fm < 4; fm++) {
        #pragma unroll
        for (int fn = 0; fn < 4; fn++) {
            int col = bn + wn + fn * 8 + qcol;
            float2 b2 = *(const float2*)&bias[col];
            #pragma unroll
            for (int h = 0; h < 2; h++) {
                int row = bm + wm + fm * 16 + qrow + h * 8;
                float vx = (acc[fm][fn][h*2+0] + b2.x) * scale;
                float vy = (acc[fm][fn][h*2+1] + b2.y) * scale;
                int hh = col >> 6, dki = col & 63;
                int bb = row >> 11, ss = row & 2047;
                size_t o = (((size_t)bb * NHEAD + hh) * SEQ + ss) * DK + dki;
                *(uint32_t*)&outh[o] = packh2(vx, vy);
            }
        }
    }
}

// ---------------------------------------------------------------------------
// Output projection: ctx(fp16) @ Wo^T + bo + x -> fp32
// ---------------------------------------------------------------------------
__global__ __launch_bounds__(256, 2) void gemm_out(
    const __half* __restrict__ C, const __half* __restrict__ W,
    const float* __restrict__ bias, const float* __restrict__ resid,
    float* __restrict__ outf)
{
    extern __shared__ char dynsmem[];
    const int tid = threadIdx.x, wid = tid >> 5, lane = tid & 31;
    const int bn = blockIdx.x * 128, bm = blockIdx.y * 128;

    float acc[4][4][4];
    #pragma unroll
    for (int i = 0; i < 4; i++)
        #pragma unroll
        for (int j = 0; j < 4; j++)
            #pragma unroll
            for (int k = 0; k < 4; k++) acc[i][j][k] = 0.f;

    gemm_core(C, W, dynsmem, tid, wid, lane, bm, bn, acc);

    const int wm = (wid >> 2) * 64, wn = (wid & 3) * 32;
    const int qrow = lane >> 2, qcol = (lane & 3) * 2;
    #pragma unroll
    for (int fm = 0; fm < 4; fm++) {
        #pragma unroll
        for (int fn = 0; fn < 4; fn++) {
            int col = bn + wn + fn * 8 + qcol;
            float2 b2 = *(const float2*)&bias[col];
            #pragma unroll
            for (int h = 0; h < 2; h++) {
                int row = bm + wm + fm * 16 + qrow + h * 8;
                float2 r2 = *(const float2*)&resid[(size_t)row * DMODEL + col];
                float vx = acc[fm][fn][h*2+0] + b2.x + r2.x;
                float vy = acc[fm][fn][h*2+1] + b2.y + r2.y;
                *(float2*)&outf[(size_t)row * DMODEL + col] = make_float2(vx, vy);
            }
        }
    }
}

// ---------------------------------------------------------------------------
// Flash attention, fp16 single-pass, cp.async 2-stage, 2 CTAs/SM.
// Stage: K 0..9216, V^T 9216..18432 (row stride 144B).
// ---------------------------------------------------------------------------
#define F_K 0
#define F_V 9216
#define FSTAGE 18432
#define FSMEM (2*FSTAGE)

__global__ __launch_bounds__(256, 2) void flash_mma()
{
    extern __shared__ char dynsmem[];
    const uint32_t smem_base = cvta_s(dynsmem);
    const int tid = threadIdx.x, wid = tid >> 5, lane = tid & 31;
    const int bh = blockIdx.y;
    const int q0 = blockIdx.x * 128;

    const __half* Q   = g_q  + (size_t)bh * SEQ * DK;
    const __half* K   = g_k  + (size_t)bh * SEQ * DK;
    const __half* Vt  = g_vt + (size_t)bh * DK * SEQ;

    const int a_row = lane & 15;
    const int a_kb  = ((lane >> 4) & 1) * 16;
    const int b_row = ((lane >> 4) & 1) * 8 + (lane & 7);
    const int b_kb  = ((lane >> 3) & 1) * 16;

    int l_r[2], l_ch[2];
    #pragma unroll
    for (int p = 0; p < 2; p++) {
        int idx = tid + p * 256;
        l_r[p] = idx >> 3;
        l_ch[p] = idx & 7;
    }

    // ---- stage Q into registers (two 64-row halves through F_K buffer) ----
    uint32_t qf[4][4];
    #pragma unroll
    for (int half = 0; half < 2; half++) {
        #pragma unroll
        for (int p = 0; p < 2; p++) {
            int r = l_r[p], ch = l_ch[p];
            uint32_t so = (uint32_t)(r * 144 + ch * 16);
            *(uint4*)(dynsmem + F_K + so) =
                *(const uint4*)&Q[(size_t)(q0 + half * 64 + r) * DK + ch * 8];
        }
        __syncthreads();
        if ((wid >> 2) == half) {
            int wr = (wid & 3) * 16;
            #pragma unroll
            for (int kc = 0; kc < 4; kc++) {
                uint32_t aa = (uint32_t)((wr + a_row) * 144 + kc * 32 + a_kb);
                ldsm_x4(qf[kc], smem_base + F_K + aa);
            }
        }
        __syncthreads();
    }

    auto load_kv = [&](int kt, int stg) {
        uint32_t base = smem_base + stg * FSTAGE;
        #pragma unroll
        for (int p = 0; p < 2; p++) {
            int r = l_r[p], ch = l_ch[p];
            uint32_t so = (uint32_t)(r * 144 + ch * 16);
            cp16(base + F_K + so, K  + (size_t)(kt + r) * DK + ch * 8);
            cp16(base + F_V + so, Vt + (size_t)r * SEQ + kt + ch * 8);
        }
        CP_COMMIT();
    };

    float m0 = -1e30f, m1 = -1e30f, l0 = 0.f, l1 = 0.f;
    float o[8][4];
    #pragma unroll
    for (int i = 0; i < 8; i++)
        #pragma unroll
        for (int j = 0; j < 4; j++) o[i][j] = 0.f;

    load_kv(0, 0);

    for (int t = 0; t < SEQ / 64; t++) {
        if (t + 1 < SEQ / 64) {
            load_kv((t + 1) * 64, (t + 1) & 1);
            CP_WAIT(1);
        } else {
            CP_WAIT(0);
        }
        __syncthreads();

        uint32_t sb = smem_base + (t & 1) * FSTAGE;
        uint32_t sk = sb + F_K, sv = sb + F_V;

        // ---- S = Q K^T (single pass; Q pre-scaled 1/8) ----
        float s[8][4];
        #pragma unroll
        for (int i = 0; i < 8; i++)
            #pragma unroll
            for (int j = 0; j < 4; j++) s[i][j] = 0.f;
        #pragma unroll
        for (int kc = 0; kc < 4; kc++) {
            #pragma unroll
            for (int f = 0; f < 4; f++) {
                uint32_t ba = (uint32_t)((f * 16 + b_row) * 144 + kc * 32 + b_kb);
                uint32_t kh4[4];
                ldsm_x4(kh4, sk + ba);
                mma16816(s[2*f+0], qf[kc], &kh4[0]);
                mma16816(s[2*f+1], qf[kc], &kh4[2]);
            }
        }

        // ---- online softmax ----
        float rm0 = -1e30f, rm1 = -1e30f;
        #pragma unroll
        for (int j = 0; j < 8; j++) {
            rm0 = fmaxf(rm0, fmaxf(s[j][0], s[j][1]));
            rm1 = fmaxf(rm1, fmaxf(s[j][2], s[j][3]));
        }
        rm0 = fmaxf(rm0, __shfl_xor_sync(0xffffffffu, rm0, 1));
        rm0 = fmaxf(rm0, __shfl_xor_sync(0xffffffffu, rm0, 2));
        rm1 = fmaxf(rm1, __shfl_xor_sync(0xffffffffu, rm1, 1));
        rm1 = fmaxf(rm1, __shfl_xor_sync(0xffffffffu, rm1, 2));
        float mn0 = fmaxf(m0, rm0), mn1 = fmaxf(m1, rm1);
        float al0 = __expf(m0 - mn0), al1 = __expf(m1 - mn1);
        float rs0 = 0.f, rs1 = 0.f;
        #pragma unroll
        for (int j = 0; j < 8; j++) {
            s[j][0] = __expf(s[j][0] - mn0);
            s[j][1] = __expf(s[j][1] - mn0);
            s[j][2] = __expf(s[j][2] - mn1);
            s[j][3] = __expf(s[j][3] - mn1);
            rs0 += s[j][0] + s[j][1];
            rs1 += s[j][2] + s[j][3];
        }
        rs0 += __shfl_xor_sync(0xffffffffu, rs0, 1);
        rs0 += __shfl_xor_sync(0xffffffffu, rs0, 2);
        rs1 += __shfl_xor_sync(0xffffffffu, rs1, 1);
        rs1 += __shfl_xor_sync(0xffffffffu, rs1, 2);
        l0 = l0 * al0 + rs0;  l1 = l1 * al1 + rs1;
        m0 = mn0;  m1 = mn1;
        #pragma unroll
        for (int j = 0; j < 8; j++) {
            o[j][0] *= al0; o[j][1] *= al0;
            o[j][2] *= al1; o[j][3] *= al1;
        }

        // ---- P -> fp16 A-fragments (register repack) ----
        uint32_t ph[4][4];
        #pragma unroll
        for (int kc = 0; kc < 4; kc++) {
            #pragma unroll
            for (int q = 0; q < 2; q++) {
                ph[kc][2*q+0] = packh2(s[2*kc+q][0], s[2*kc+q][1]);
                ph[kc][2*q+1] = packh2(s[2*kc+q][2], s[2*kc+q][3]);
            }
        }

        // ---- O += P V (single pass) ----
        #pragma unroll
        for (int f = 0; f < 4; f++) {
            #pragma unroll
            for (int kc = 0; kc < 4; kc++) {
                uint32_t ba = (uint32_t)((f * 16 + b_row) * 144 + kc * 32 + b_kb);
                uint32_t vh4[4];
                ldsm_x4(vh4, sv + ba);
                mma16816(o[2*f+0], ph[kc], &vh4[0]);
                mma16816(o[2*f+1], ph[kc], &vh4[2]);
            }
        }
        __syncthreads();
    }

    // ---- write ctx fp16 [t][dmodel] ----
    const int b = bh >> 4, h = bh & 15;
    const int r0 = q0 + wid * 16 + (lane >> 2);
    float inv0 = 1.f / l0, inv1 = 1.f / l1;
    #pragma unroll
    for (int f = 0; f < 8; f++) {
        int col = h * DK + f * 8 + (lane & 3) * 2;
        size_t o0 = (size_t)(b * SEQ + r0    ) * DMODEL + col;
        size_t o1 = (size_t)(b * SEQ + r0 + 8) * DMODEL + col;
        *(uint32_t*)&g_c[o0] = packh2(o[f][0] * inv0, o[f][1] * inv0);
        *(uint32_t*)&g_c[o1] = packh2(o[f][2] * inv1, o[f][3] * inv1);
    }
}

// ---------------------------------------------------------------------------
// LayerNorm
// ---------------------------------------------------------------------------
__global__ __launch_bounds__(256) void ln_fused(
    const float* __restrict__ Y, const float* __restrict__ gamma,
    const float* __restrict__ beta, float* __restrict__ out)
{
    __shared__ float s_sum[8], s_sq[8];
    const int t = blockIdx.x;
    const int tid = threadIdx.x;
    const float* row = Y + (size_t)t * DMODEL;
    float4 v = *(const float4*)&row[tid * 4];
    float sum = v.x + v.y + v.z + v.w;
    float sq  = v.x*v.x + v.y*v.y + v.z*v.z + v.w*v.w;
    #pragma unroll
    for (int off = 16; off; off >>= 1) {
        sum += __shfl_xor_sync(0xffffffffu, sum, off);
        sq  += __shfl_xor_sync(0xffffffffu, sq,  off);
    }
    int w = tid >> 5;
    if ((tid & 31) == 0) { s_sum[w] = sum; s_sq[w] = sq; }
    __syncthreads();
    if (tid < 32) {
        sum = (tid < 8) ? s_sum[tid] : 0.f;
        sq  = (tid < 8) ? s_sq[tid]  : 0.f;
        #pragma unroll
        for (int off = 4; off; off >>= 1) {
            sum += __shfl_xor_sync(0xffffffffu, sum, off);
            sq  += __shfl_xor_sync(0xffffffffu, sq,  off);
        }
        if (tid == 0) { s_sum[0] = sum; s_sq[0] = sq; }
    }
    __syncthreads();
    float mu  = s_sum[0] * (1.f / DMODEL);
    float var = s_sq[0]  * (1.f / DMODEL) - mu * mu;
    float rstd = rsqrtf(var + 1e-5f);
    float4 g  = *(const float4*)&gamma[tid * 4];
    float4 bt = *(const float4*)&beta[tid * 4];
    float4 o4;
    o4.x = (v.x - mu) * rstd * g.x + bt.x;
    o4.y = (v.y - mu) * rstd * g.y + bt.y;
    o4.z = (v.z - mu) * rstd * g.z + bt.z;
    o4.w = (v.w - mu) * rstd * g.w + bt.w;
    *(float4*)&out[(size_t)t * DMODEL + tid * 4] = o4;
}

// ---------------------------------------------------------------------------
extern "C" void kernel_launch(void* const* d_in, const int* in_sizes, int n_in,
                              void* d_out, int out_size)
{
    const float* x     = (const float*)d_in[0];
    const float* Wq    = (const float*)d_in[1];
    const float* bq    = (const float*)d_in[2];
    const float* Wk    = (const float*)d_in[3];
    const float* bk    = (const float*)d_in[4];
    const float* Wv    = (const float*)d_in[5];
    const float* bv    = (const float*)d_in[6];
    const float* Wo    = (const float*)d_in[7];
    const float* bo    = (const float*)d_in[8];
    const float* gamma = (const float*)d_in[9];
    const float* beta  = (const float*)d_in[10];
    float* out = (float*)d_out;
    (void)in_sizes; (void)n_in; (void)out_size;

    float* gy;
    __half *x16, *w16, *q, *k, *vs, *vt, *c;
    cudaGetSymbolAddress((void**)&gy,  g_Y);
    cudaGetSymbolAddress((void**)&x16, g_x16);
    cudaGetSymbolAddress((void**)&w16, g_w16);
    cudaGetSymbolAddress((void**)&q,   g_q);
    cudaGetSymbolAddress((void**)&k,   g_k);
    cudaGetSymbolAddress((void**)&vs,  g_vs);
    cudaGetSymbolAddress((void**)&vt,  g_vt);
    cudaGetSymbolAddress((void**)&c,   g_c);

    static bool attr_done = false;
    if (!attr_done) {
        cudaFuncSetAttribute(gemm_qkv, cudaFuncAttributeMaxDynamicSharedMemorySize, GSMEM);
        cudaFuncSetAttribute(gemm_out, cudaFuncAttributeMaxDynamicSharedMemorySize, GSMEM);
        cudaFuncSetAttribute(flash_mma, cudaFuncAttributeMaxDynamicSharedMemorySize, FSMEM);
        attr_done = true;
    }

    const int nx4 = NTOK * DMODEL / 4;
    const int nw4 = WELEM / 4;

    conv_f16<<<(nx4 + 255) / 256, 256>>>(x, x16, nx4);
    conv_f16<<<(nw4 + 255) / 256, 256>>>(Wq, w16 + 0*(size_t)WELEM, nw4);
    conv_f16<<<(nw4 + 255) / 256, 256>>>(Wk, w16 + 1*(size_t)WELEM, nw4);
    conv_f16<<<(nw4 + 255) / 256, 256>>>(Wv, w16 + 2*(size_t)WELEM, nw4);
    conv_f16<<<(nw4 + 255) / 256, 256>>>(Wo, w16 + 3*(size_t)WELEM, nw4);

    // merged Q/K/V projection: 3 weights x 8 n-tiles x 64 m-tiles
    gemm_qkv<<<dim3(24, NTOK / 128), 256, GSMEM>>>(x16, w16, bq, bk, bv, q, k, vs);
    conv_trans<<<dim3(SEQ / 32, DK / 32, BHTOT), 256>>>(vs, vt);

    flash_mma<<<dim3(SEQ / 128, BHTOT), 256, FSMEM>>>();

    gemm_out<<<dim3(DMODEL / 128, NTOK / 128), 256, GSMEM>>>(
        c, w16 + 3*(size_t)WELEM, bo, x, gy);

    ln_fused<<<NTOK, 256>>>(gy, gamma, beta, out);
}

// round 9
// speedup vs baseline: 8.5479x; 1.0244x over previous
#include <cuda_runtime.h>
#include <cuda_fp16.h>
#include <cstdint>

#define BATCH 4
#define SEQ   2048
#define DMODEL 1024
#define NHEAD 16
#define DK    64
#define NTOK  (BATCH*SEQ)    // 8192
#define BHTOT (BATCH*NHEAD)  // 64
#define WELEM (DMODEL*DMODEL)

// Scratch (static device globals — allocation-free per harness rules)
__device__ float  g_Y[(size_t)NTOK*DMODEL];
__device__ __half g_x16[(size_t)NTOK*DMODEL];
__device__ __half g_w16[(size_t)4*WELEM];
__device__ __half g_q[(size_t)BHTOT*SEQ*DK];    // pre-scaled by 0.125
__device__ __half g_k[(size_t)BHTOT*SEQ*DK];
__device__ __half g_v[(size_t)BHTOT*SEQ*DK];    // V [bh][s][dk] (natural)
__device__ __half g_c[(size_t)NTOK*DMODEL];     // ctx fp16

// ---------------------------------------------------------------------------
// helpers
// ---------------------------------------------------------------------------
__device__ __forceinline__ void ldsm_x4(uint32_t (&r)[4], uint32_t addr) {
    asm volatile("ldmatrix.sync.aligned.m8n8.x4.shared.b16 {%0,%1,%2,%3}, [%4];"
        : "=r"(r[0]), "=r"(r[1]), "=r"(r[2]), "=r"(r[3]) : "r"(addr));
}
__device__ __forceinline__ void ldsm_x4_t(uint32_t (&r)[4], uint32_t addr) {
    asm volatile("ldmatrix.sync.aligned.m8n8.x4.trans.shared.b16 {%0,%1,%2,%3}, [%4];"
        : "=r"(r[0]), "=r"(r[1]), "=r"(r[2]), "=r"(r[3]) : "r"(addr));
}
__device__ __forceinline__ void mma16816(float* d, const uint32_t* a, const uint32_t* b) {
    asm volatile(
        "mma.sync.aligned.m16n8k16.row.col.f32.f16.f16.f32 "
        "{%0,%1,%2,%3}, {%4,%5,%6,%7}, {%8,%9}, {%0,%1,%2,%3};"
        : "+f"(d[0]), "+f"(d[1]), "+f"(d[2]), "+f"(d[3])
        : "r"(a[0]), "r"(a[1]), "r"(a[2]), "r"(a[3]), "r"(b[0]), "r"(b[1]));
}
__device__ __forceinline__ uint32_t cvta_s(const void* p) {
    uint32_t a;
    asm("{ .reg .u64 t; cvta.to.shared.u64 t, %1; cvt.u32.u64 %0, t; }" : "=r"(a) : "l"(p));
    return a;
}
__device__ __forceinline__ uint32_t packh2(float x, float y) {
    __half2 t(__float2half_rn(x), __float2half_rn(y));
    return *reinterpret_cast<uint32_t*>(&t);
}
__device__ __forceinline__ void cp16(uint32_t dst, const void* src) {
    asm volatile("cp.async.ca.shared.global [%0], [%1], 16;" :: "r"(dst), "l"(src));
}
#define CP_COMMIT()  asm volatile("cp.async.commit_group;" ::: "memory")
#define CP_WAIT(N)   asm volatile("cp.async.wait_group %0;" :: "n"(N) : "memory")

// ---------------------------------------------------------------------------
// Merged fp32 -> fp16 conversion: x (NX4 quads) then Wq|Wk|Wv|Wo (WQ4 each,
// contiguous destination g_w16).
// ---------------------------------------------------------------------------
#define NX4 (NTOK*DMODEL/4)      // 2097152 quads
#define WQ4 (WELEM/4)            // 262144 quads (1<<18)

__global__ __launch_bounds__(256) void conv_all(
    const float* __restrict__ x,
    const float* __restrict__ Wq, const float* __restrict__ Wk,
    const float* __restrict__ Wv, const float* __restrict__ Wo,
    __half* __restrict__ x16, __half* __restrict__ w16)
{
    int i = blockIdx.x * blockDim.x + threadIdx.x;
    const float* src;
    __half* dst;
    size_t off;
    if (i < NX4) {
        src = x; dst = x16; off = (size_t)i;
    } else {
        int w = i - NX4;
        int seg = w >> 18;
        const float* Ws[4] = {Wq, Wk, Wv, Wo};
        src = Ws[seg];
        dst = w16 + (size_t)seg * WELEM;
        off = (size_t)(w & (WQ4 - 1));
    }
    float4 v = *(const float4*)&src[off * 4];
    __half2 A(__float2half_rn(v.x), __float2half_rn(v.y));
    __half2 B(__float2half_rn(v.z), __float2half_rn(v.w));
    *(uint2*)&dst[off * 4] = make_uint2(*(uint32_t*)&A, *(uint32_t*)&B);
}

// ---------------------------------------------------------------------------
// GEMM core (fp16 single-pass): acc[t,e] = sum_d A[t,d]*B[e,d]
// CTA 128x128, K-chunk 32, cp.async 2-stage. smem row stride 80B.
// ---------------------------------------------------------------------------
#define G_A 0
#define G_B 10240
#define GSTAGE 20480
#define GSMEM (2*GSTAGE)

__device__ __forceinline__ void gemm_core(
    const __half* __restrict__ A, const __half* __restrict__ B,
    char* dynsmem, int tid, int wid, int lane, int bm, int bn,
    float (&acc)[4][4][4])
{
    const uint32_t smem_base = cvta_s(dynsmem);
    const int wm = (wid >> 2) * 64, wn = (wid & 3) * 32;
    const int a_row = lane & 15;
    const int a_kb  = ((lane >> 4) & 1) * 16;
    const int b_row = ((lane >> 4) & 1) * 8 + (lane & 7);
    const int b_kb  = ((lane >> 3) & 1) * 16;

    int l_r[2], l_ch[2];
    #pragma unroll
    for (int p = 0; p < 2; p++) {
        int idx = tid + p * 256;
        l_r[p] = idx >> 2;
        l_ch[p] = idx & 3;
    }

    auto load_chunk = [&](int c, int stg) {
        const int k0 = c * 32;
        uint32_t base = smem_base + stg * GSTAGE;
        #pragma unroll
        for (int p = 0; p < 2; p++) {
            int r = l_r[p], ch = l_ch[p];
            uint32_t so = (uint32_t)(r * 80 + ch * 16);
            cp16(base + G_A + so, A + (size_t)(bm + r) * DMODEL + k0 + ch * 8);
            cp16(base + G_B + so, B + (size_t)(bn + r) * DMODEL + k0 + ch * 8);
        }
        CP_COMMIT();
    };

    load_chunk(0, 0);

    for (int c = 0; c < DMODEL / 32; c++) {
        if (c + 1 < DMODEL / 32) {
            load_chunk(c + 1, (c + 1) & 1);
            CP_WAIT(1);
        } else {
            CP_WAIT(0);
        }
        __syncthreads();

        uint32_t sb = smem_base + (c & 1) * GSTAGE;
        uint32_t sa = sb + G_A, sbh = sb + G_B;

        #pragma unroll
        for (int ks = 0; ks < 2; ks++) {
            const int kbase = ks * 32;
            uint32_t bhf[4][2];
            #pragma unroll
            for (int fp = 0; fp < 2; fp++) {
                uint32_t r4[4];
                uint32_t ba = (uint32_t)((wn + fp * 16 + b_row) * 80 + kbase + b_kb);
                ldsm_x4(r4, sbh + ba);
                bhf[fp*2+0][0] = r4[0]; bhf[fp*2+0][1] = r4[1];
                bhf[fp*2+1][0] = r4[2]; bhf[fp*2+1][1] = r4[3];
            }
            #pragma unroll
            for (int fm = 0; fm < 4; fm++) {
                uint32_t aa = (uint32_t)((wm + fm * 16 + a_row) * 80 + kbase + a_kb);
                uint32_t af[4];
                ldsm_x4(af, sa + aa);
                #pragma unroll
                for (int fn = 0; fn < 4; fn++)
                    mma16816(acc[fm][fn], af, bhf[fn]);
            }
        }
        __syncthreads();
    }
}

// ---------------------------------------------------------------------------
// Merged QKV projection: grid.x = 24 (3 weights x 8 n-tiles), grid.y = 64.
// Writes fp16 [b,h,s,dk]; Q scaled by 0.125. V natural (same layout as K).
// ---------------------------------------------------------------------------
__global__ __launch_bounds__(256, 2) void gemm_qkv(
    const __half* __restrict__ X, const __half* __restrict__ W,
    const float* __restrict__ bq, const float* __restrict__ bk,
    const float* __restrict__ bv,
    __half* __restrict__ outq, __half* __restrict__ outk,
    __half* __restrict__ outv)
{
    extern __shared__ char dynsmem[];
    const int tid = threadIdx.x, wid = tid >> 5, lane = tid & 31;
    const int which = blockIdx.x >> 3;
    const int bn = (blockIdx.x & 7) * 128;
    const int bm = blockIdx.y * 128;

    const __half* B = W + (size_t)which * WELEM;
    const float* bias = (which == 0) ? bq : (which == 1) ? bk : bv;
    __half* outh = (which == 0) ? outq : (which == 1) ? outk : outv;
    const float scale = (which == 0) ? 0.125f : 1.f;

    float acc[4][4][4];
    #pragma unroll
    for (int i = 0; i < 4; i++)
        #pragma unroll
        for (int j = 0; j < 4; j++)
            #pragma unroll
            for (int k = 0; k < 4; k++) acc[i][j][k] = 0.f;

    gemm_core(X, B, dynsmem, tid, wid, lane, bm, bn, acc);

    const int wm = (wid >> 2) * 64, wn = (wid & 3) * 32;
    const int qrow = lane >> 2, qcol = (lane & 3) * 2;
    #pragma unroll
    for (int fm = 0; fm < 4; fm++) {
        #pragma unroll
        for (int fn = 0; fn < 4; fn++) {
            int col = bn + wn + fn * 8 + qcol;
            float2 b2 = *(const float2*)&bias[col];
            #pragma unroll
            for (int h = 0; h < 2; h++) {
                int row = bm + wm + fm * 16 + qrow + h * 8;
                float vx = (acc[fm][fn][h*2+0] + b2.x) * scale;
                float vy = (acc[fm][fn][h*2+1] + b2.y) * scale;
                int hh = col >> 6, dki = col & 63;
                int bb = row >> 11, ss = row & 2047;
                size_t o = (((size_t)bb * NHEAD + hh) * SEQ + ss) * DK + dki;
                *(uint32_t*)&outh[o] = packh2(vx, vy);
            }
        }
    }
}

// ---------------------------------------------------------------------------
// Output projection: ctx(fp16) @ Wo^T + bo + x -> fp32
// ---------------------------------------------------------------------------
__global__ __launch_bounds__(256, 2) void gemm_out(
    const __half* __restrict__ C, const __half* __restrict__ W,
    const float* __restrict__ bias, const float* __restrict__ resid,
    float* __restrict__ outf)
{
    extern __shared__ char dynsmem[];
    const int tid = threadIdx.x, wid = tid >> 5, lane = tid & 31;
    const int bn = blockIdx.x * 128, bm = blockIdx.y * 128;

    float acc[4][4][4];
    #pragma unroll
    for (int i = 0; i < 4; i++)
        #pragma unroll
        for (int j = 0; j < 4; j++)
            #pragma unroll
            for (int k = 0; k < 4; k++) acc[i][j][k] = 0.f;

    gemm_core(C, W, dynsmem, tid, wid, lane, bm, bn, acc);

    const int wm = (wid >> 2) * 64, wn = (wid & 3) * 32;
    const int qrow = lane >> 2, qcol = (lane & 3) * 2;
    #pragma unroll
    for (int fm = 0; fm < 4; fm++) {
        #pragma unroll
        for (int fn = 0; fn < 4; fn++) {
            int col = bn + wn + fn * 8 + qcol;
            float2 b2 = *(const float2*)&bias[col];
            #pragma unroll
            for (int h = 0; h < 2; h++) {
                int row = bm + wm + fm * 16 + qrow + h * 8;
                float2 r2 = *(const float2*)&resid[(size_t)row * DMODEL + col];
                float vx = acc[fm][fn][h*2+0] + b2.x + r2.x;
                float vy = acc[fm][fn][h*2+1] + b2.y + r2.y;
                *(float2*)&outf[(size_t)row * DMODEL + col] = make_float2(vx, vy);
            }
        }
    }
}

// ---------------------------------------------------------------------------
// Flash attention, fp16 single-pass, cp.async 2-stage, 2 CTAs/SM.
// K and V tiles both [kv][dk] natural layout (row stride 144B).
// P·V B-frags via ldmatrix.trans directly from natural V.
// ---------------------------------------------------------------------------
#define F_K 0
#define F_V 9216
#define FSTAGE 18432
#define FSMEM (2*FSTAGE)

__global__ __launch_bounds__(256, 2) void flash_mma()
{
    extern __shared__ char dynsmem[];
    const uint32_t smem_base = cvta_s(dynsmem);
    const int tid = threadIdx.x, wid = tid >> 5, lane = tid & 31;
    const int bh = blockIdx.y;
    const int q0 = blockIdx.x * 128;

    const __half* Q = g_q + (size_t)bh * SEQ * DK;
    const __half* K = g_k + (size_t)bh * SEQ * DK;
    const __half* V = g_v + (size_t)bh * SEQ * DK;

    const int a_row = lane & 15;
    const int a_kb  = ((lane >> 4) & 1) * 16;
    const int b_row = ((lane >> 4) & 1) * 8 + (lane & 7);
    const int b_kb  = ((lane >> 3) & 1) * 16;
    // trans-ldmatrix lane map for V (natural [kv][dk]):
    const int v_row = lane & 15;                 // kv row within 16
    const int v_cb  = ((lane >> 4) & 1) * 16;    // dk 8-group byte offset

    int l_r[2], l_ch[2];
    #pragma unroll
    for (int p = 0; p < 2; p++) {
        int idx = tid + p * 256;
        l_r[p] = idx >> 3;
        l_ch[p] = idx & 7;
    }

    // ---- stage Q into registers (two 64-row halves through F_K buffer) ----
    uint32_t qf[4][4];
    #pragma unroll
    for (int half = 0; half < 2; half++) {
        #pragma unroll
        for (int p = 0; p < 2; p++) {
            int r = l_r[p], ch = l_ch[p];
            uint32_t so = (uint32_t)(r * 144 + ch * 16);
            *(uint4*)(dynsmem + F_K + so) =
                *(const uint4*)&Q[(size_t)(q0 + half * 64 + r) * DK + ch * 8];
        }
        __syncthreads();
        if ((wid >> 2) == half) {
            int wr = (wid & 3) * 16;
            #pragma unroll
            for (int kc = 0; kc < 4; kc++) {
                uint32_t aa = (uint32_t)((wr + a_row) * 144 + kc * 32 + a_kb);
                ldsm_x4(qf[kc], smem_base + F_K + aa);
            }
        }
        __syncthreads();
    }

    auto load_kv = [&](int kt, int stg) {
        uint32_t base = smem_base + stg * FSTAGE;
        #pragma unroll
        for (int p = 0; p < 2; p++) {
            int r = l_r[p], ch = l_ch[p];
            uint32_t so = (uint32_t)(r * 144 + ch * 16);
            cp16(base + F_K + so, K + (size_t)(kt + r) * DK + ch * 8);
            cp16(base + F_V + so, V + (size_t)(kt + r) * DK + ch * 8);
        }
        CP_COMMIT();
    };

    float m0 = -1e30f, m1 = -1e30f, l0 = 0.f, l1 = 0.f;
    float o[8][4];
    #pragma unroll
    for (int i = 0; i < 8; i++)
        #pragma unroll
        for (int j = 0; j < 4; j++) o[i][j] = 0.f;

    load_kv(0, 0);

    for (int t = 0; t < SEQ / 64; t++) {
        if (t + 1 < SEQ / 64) {
            load_kv((t + 1) * 64, (t + 1) & 1);
            CP_WAIT(1);
        } else {
            CP_WAIT(0);
        }
        __syncthreads();

        uint32_t sb = smem_base + (t & 1) * FSTAGE;
        uint32_t sk = sb + F_K, sv = sb + F_V;

        // ---- S = Q K^T (single pass; Q pre-scaled 1/8) ----
        float s[8][4];
        #pragma unroll
        for (int i = 0; i < 8; i++)
            #pragma unroll
            for (int j = 0; j < 4; j++) s[i][j] = 0.f;
        #pragma unroll
        for (int kc = 0; kc < 4; kc++) {
            #pragma unroll
            for (int f = 0; f < 4; f++) {
                uint32_t ba = (uint32_t)((f * 16 + b_row) * 144 + kc * 32 + b_kb);
                uint32_t kh4[4];
                ldsm_x4(kh4, sk + ba);
                mma16816(s[2*f+0], qf[kc], &kh4[0]);
                mma16816(s[2*f+1], qf[kc], &kh4[2]);
            }
        }

        // ---- online softmax ----
        float rm0 = -1e30f, rm1 = -1e30f;
        #pragma unroll
        for (int j = 0; j < 8; j++) {
            rm0 = fmaxf(rm0, fmaxf(s[j][0], s[j][1]));
            rm1 = fmaxf(rm1, fmaxf(s[j][2], s[j][3]));
        }
        rm0 = fmaxf(rm0, __shfl_xor_sync(0xffffffffu, rm0, 1));
        rm0 = fmaxf(rm0, __shfl_xor_sync(0xffffffffu, rm0, 2));
        rm1 = fmaxf(rm1, __shfl_xor_sync(0xffffffffu, rm1, 1));
        rm1 = fmaxf(rm1, __shfl_xor_sync(0xffffffffu, rm1, 2));
        float mn0 = fmaxf(m0, rm0), mn1 = fmaxf(m1, rm1);
        float al0 = __expf(m0 - mn0), al1 = __expf(m1 - mn1);
        float rs0 = 0.f, rs1 = 0.f;
        #pragma unroll
        for (int j = 0; j < 8; j++) {
            s[j][0] = __expf(s[j][0] - mn0);
            s[j][1] = __expf(s[j][1] - mn0);
            s[j][2] = __expf(s[j][2] - mn1);
            s[j][3] = __expf(s[j][3] - mn1);
            rs0 += s[j][0] + s[j][1];
            rs1 += s[j][2] + s[j][3];
        }
        rs0 += __shfl_xor_sync(0xffffffffu, rs0, 1);
        rs0 += __shfl_xor_sync(0xffffffffu, rs0, 2);
        rs1 += __shfl_xor_sync(0xffffffffu, rs1, 1);
        rs1 += __shfl_xor_sync(0xffffffffu, rs1, 2);
        l0 = l0 * al0 + rs0;  l1 = l1 * al1 + rs1;
        m0 = mn0;  m1 = mn1;
        #pragma unroll
        for (int j = 0; j < 8; j++) {
            o[j][0] *= al0; o[j][1] *= al0;
            o[j][2] *= al1; o[j][3] *= al1;
        }

        // ---- P -> fp16 A-fragments (register repack) ----
        uint32_t ph[4][4];
        #pragma unroll
        for (int kc = 0; kc < 4; kc++) {
            #pragma unroll
            for (int q = 0; q < 2; q++) {
                ph[kc][2*q+0] = packh2(s[2*kc+q][0], s[2*kc+q][1]);
                ph[kc][2*q+1] = packh2(s[2*kc+q][2], s[2*kc+q][3]);
            }
        }

        // ---- O += P V (single pass; B-frags via ldmatrix.trans on natural V) ----
        #pragma unroll
        for (int f = 0; f < 4; f++) {
            #pragma unroll
            for (int kc = 0; kc < 4; kc++) {
                uint32_t va = (uint32_t)((kc * 16 + v_row) * 144 + f * 32 + v_cb);
                uint32_t vh4[4];
                ldsm_x4_t(vh4, sv + va);
                mma16816(o[2*f+0], ph[kc], &vh4[0]);
                mma16816(o[2*f+1], ph[kc], &vh4[2]);
            }
        }
        __syncthreads();
    }

    // ---- write ctx fp16 [t][dmodel] ----
    const int b = bh >> 4, h = bh & 15;
    const int r0 = q0 + wid * 16 + (lane >> 2);
    float inv0 = 1.f / l0, inv1 = 1.f / l1;
    #pragma unroll
    for (int f = 0; f < 8; f++) {
        int col = h * DK + f * 8 + (lane & 3) * 2;
        size_t o0 = (size_t)(b * SEQ + r0    ) * DMODEL + col;
        size_t o1 = (size_t)(b * SEQ + r0 + 8) * DMODEL + col;
        *(uint32_t*)&g_c[o0] = packh2(o[f][0] * inv0, o[f][1] * inv0);
        *(uint32_t*)&g_c[o1] = packh2(o[f][2] * inv1, o[f][3] * inv1);
    }
}

// ---------------------------------------------------------------------------
// LayerNorm
// ---------------------------------------------------------------------------
__global__ __launch_bounds__(256) void ln_fused(
    const float* __restrict__ Y, const float* __restrict__ gamma,
    const float* __restrict__ beta, float* __restrict__ out)
{
    __shared__ float s_sum[8], s_sq[8];
    const int t = blockIdx.x;
    const int tid = threadIdx.x;
    const float* row = Y + (size_t)t * DMODEL;
    float4 v = *(const float4*)&row[tid * 4];
    float sum = v.x + v.y + v.z + v.w;
    float sq  = v.x*v.x + v.y*v.y + v.z*v.z + v.w*v.w;
    #pragma unroll
    for (int off = 16; off; off >>= 1) {
        sum += __shfl_xor_sync(0xffffffffu, sum, off);
        sq  += __shfl_xor_sync(0xffffffffu, sq,  off);
    }
    int w = tid >> 5;
    if ((tid & 31) == 0) { s_sum[w] = sum; s_sq[w] = sq; }
    __syncthreads();
    if (tid < 32) {
        sum = (tid < 8) ? s_sum[tid] : 0.f;
        sq  = (tid < 8) ? s_sq[tid]  : 0.f;
        #pragma unroll
        for (int off = 4; off; off >>= 1) {
            sum += __shfl_xor_sync(0xffffffffu, sum, off);
            sq  += __shfl_xor_sync(0xffffffffu, sq,  off);
        }
        if (tid == 0) { s_sum[0] = sum; s_sq[0] = sq; }
    }
    __syncthreads();
    float mu  = s_sum[0] * (1.f / DMODEL);
    float var = s_sq[0]  * (1.f / DMODEL) - mu * mu;
    float rstd = rsqrtf(var + 1e-5f);
    float4 g  = *(const float4*)&gamma[tid * 4];
    float4 bt = *(const float4*)&beta[tid * 4];
    float4 o4;
    o4.x = (v.x - mu) * rstd * g.x + bt.x;
    o4.y = (v.y - mu) * rstd * g.y + bt.y;
    o4.z = (v.z - mu) * rstd * g.z + bt.z;
    o4.w = (v.w - mu) * rstd * g.w + bt.w;
    *(float4*)&out[(size_t)t * DMODEL + tid * 4] = o4;
}

// ---------------------------------------------------------------------------
extern "C" void kernel_launch(void* const* d_in, const int* in_sizes, int n_in,
                              void* d_out, int out_size)
{
    const float* x     = (const float*)d_in[0];
    const float* Wq    = (const float*)d_in[1];
    const float* bq    = (const float*)d_in[2];
    const float* Wk    = (const float*)d_in[3];
    const float* bk    = (const float*)d_in[4];
    const float* Wv    = (const float*)d_in[5];
    const float* bv    = (const float*)d_in[6];
    const float* Wo    = (const float*)d_in[7];
    const float* bo    = (const float*)d_in[8];
    const float* gamma = (const float*)d_in[9];
    const float* beta  = (const float*)d_in[10];
    float* out = (float*)d_out;
    (void)in_sizes; (void)n_in; (void)out_size;

    float* gy;
    __half *x16, *w16, *q, *k, *v, *c;
    cudaGetSymbolAddress((void**)&gy,  g_Y);
    cudaGetSymbolAddress((void**)&x16, g_x16);
    cudaGetSymbolAddress((void**)&w16, g_w16);
    cudaGetSymbolAddress((void**)&q,   g_q);
    cudaGetSymbolAddress((void**)&k,   g_k);
    cudaGetSymbolAddress((void**)&v,   g_v);
    cudaGetSymbolAddress((void**)&c,   g_c);

    static bool attr_done = false;
    if (!attr_done) {
        cudaFuncSetAttribute(gemm_qkv, cudaFuncAttributeMaxDynamicSharedMemorySize, GSMEM);
        cudaFuncSetAttribute(gemm_out, cudaFuncAttributeMaxDynamicSharedMemorySize, GSMEM);
        cudaFuncSetAttribute(flash_mma, cudaFuncAttributeMaxDynamicSharedMemorySize, FSMEM);
        attr_done = true;
    }

    // single merged conversion launch (x + 4 weights)
    const int total_quads = NX4 + 4 * WQ4;
    conv_all<<<(total_quads + 255) / 256, 256>>>(x, Wq, Wk, Wv, Wo, x16, w16);

    // merged Q/K/V projection: 3 weights x 8 n-tiles x 64 m-tiles
    gemm_qkv<<<dim3(24, NTOK / 128), 256, GSMEM>>>(x16, w16, bq, bk, bv, q, k, v);

    flash_mma<<<dim3(SEQ / 128, BHTOT), 256, FSMEM>>>();

    gemm_out<<<dim3(DMODEL / 128, NTOK / 128), 256, GSMEM>>>(
        c, w16 + 3*(size_t)WELEM, bo, x, gy);

    ln_fused<<<NTOK, 256>>>(gy, gamma, beta, out);
}